// round 1
// baseline (speedup 1.0000x reference)
#include <cuda_runtime.h>

#define NN   10240
#define NE   320000
#define BBG  64
#define NPGX 160
#define KF   16
#define DIN  25
#define DD   256

// ---------------- device scratch (static, allocation-free) ----------------
__device__ int   g_deg[NN];
__device__ int   g_off[NN + 1];
__device__ int   g_cur[NN];
__device__ float g_dinv[NN];
__device__ int   g_csr[NE];    // (src<<1) | mask
__device__ float g_w[NE];      // edge norm
__device__ int   g_frag[NN];
__device__ int   g_mask_is_int;
__device__ float g_H[2][NN * DD];
__device__ float g_AGI[NN * DD];
__device__ float g_AGO[NN * DD];
__device__ float g_AGI0[NN * 32];
__device__ float g_AGO0[NN * 32];

// ---------------- setup ----------------
__global__ void k_init(const float* __restrict__ s) {
    int n = blockIdx.x * blockDim.x + threadIdx.x;
    if (n >= NN) return;
    g_deg[n] = 0;
    g_cur[n] = 0;
    int f = 0;
#pragma unroll
    for (int k = 0; k < KF; k++)
        if (s[n * KF + k] > 0.5f) f = k;
    g_frag[n] = f;
}

__global__ void k_deg(const int* __restrict__ dst) {
    int e = blockIdx.x * blockDim.x + threadIdx.x;
    if (e < NE) atomicAdd(&g_deg[dst[e]], 1);
}

// Single-block scan: exclusive prefix of deg -> off; also dinv; also mask-dtype detect.
__global__ void k_scan(const unsigned char* __restrict__ maskb) {
    __shared__ int sh[1024];
    __shared__ int s_carry;
    __shared__ int s_flag;
    int t = threadIdx.x;
    if (t == 0) { s_carry = 0; s_flag = 0; }
    __syncthreads();
    // mask dtype detect: int32 0/1 encoding has zero bytes at idx%4 != 0
    {
        int idx = t * 4;
        int nz = (int)maskb[idx + 1] | (int)maskb[idx + 2] | (int)maskb[idx + 3];
        if (nz) atomicOr(&s_flag, 1);
    }
    __syncthreads();
    if (t == 0) g_mask_is_int = (s_flag == 0) ? 1 : 0;

    for (int c = 0; c < NN; c += 1024) {
        int v = g_deg[c + t];
        g_dinv[c + t] = rsqrtf((float)(v > 0 ? v : 1));
        sh[t] = v;
        __syncthreads();
        for (int o = 1; o < 1024; o <<= 1) {
            int add = (t >= o) ? sh[t - o] : 0;
            __syncthreads();
            sh[t] += add;
            __syncthreads();
        }
        g_off[c + t] = s_carry + sh[t] - v;
        __syncthreads();
        if (t == 0) s_carry += sh[1023];
        __syncthreads();
    }
    if (t == 0) g_off[NN] = s_carry;
}

__global__ void k_csr(const int* __restrict__ src, const int* __restrict__ dst,
                      const void* __restrict__ maskp) {
    int e = blockIdx.x * blockDim.x + threadIdx.x;
    if (e >= NE) return;
    int u = src[e], v = dst[e];
    int mb;
    if (g_mask_is_int) mb = (((const int*)maskp)[e] != 0) ? 1 : 0;
    else               mb = (((const unsigned char*)maskp)[e] != 0) ? 1 : 0;
    int p = g_off[v] + atomicAdd(&g_cur[v], 1);
    g_csr[p] = (u << 1) | mb;
    g_w[p]   = g_dinv[u] * g_dinv[v];
}

// ---------------- layer 0: SpMM on 25-dim input ----------------
__global__ void k_spmm0(const float* __restrict__ x) {
    int warp = threadIdx.x >> 5;
    int lane = threadIdx.x & 31;
    int n = blockIdx.x * 8 + warp;
    if (n >= NN) return;
    int beg = g_off[n], end = g_off[n + 1];
    float ai = 0.f, ao = 0.f;
    for (int j = beg; j < end; j++) {
        int sm = g_csr[j];
        float w = g_w[j];
        float v = 0.f;
        if (lane < DIN) v = x[(sm >> 1) * DIN + lane];
        if (sm & 1) ai = fmaf(w, v, ai); else ao = fmaf(w, v, ao);
    }
    if (lane < DIN) {
        g_AGI0[n * 32 + lane] = ai;
        g_AGO0[n * 32 + lane] = ao;
    }
}

// layer 0 GEMM (K=25+25) fused with bias + LN + ReLU -> g_H[0]
__global__ void k_layer0(const float* __restrict__ Wi, const float* __restrict__ Wo,
                         const float* __restrict__ bi, const float* __restrict__ bo,
                         const float* __restrict__ lg, const float* __restrict__ lb) {
    int n = blockIdx.x, t = threadIdx.x;
    __shared__ float sai[DIN], sao[DIN];
    __shared__ float r1[256], r2[256];
    if (t < DIN) { sai[t] = g_AGI0[n * 32 + t]; sao[t] = g_AGO0[n * 32 + t]; }
    __syncthreads();
    float acc = bi[t] + bo[t];
#pragma unroll
    for (int j = 0; j < DIN; j++)
        acc += sai[j] * Wi[j * DD + t] + sao[j] * Wo[j * DD + t];
    r1[t] = acc; r2[t] = acc * acc;
    __syncthreads();
    for (int o = 128; o > 0; o >>= 1) {
        if (t < o) { r1[t] += r1[t + o]; r2[t] += r2[t + o]; }
        __syncthreads();
    }
    float m = r1[0] * (1.f / DD);
    float var = r2[0] * (1.f / DD) - m * m;
    float y = (acc - m) * rsqrtf(var + 1e-5f) * lg[t] + lb[t];
    g_H[0][n * DD + t] = y > 0.f ? y : 0.f;
}

// ---------------- per-layer SpMM (D=256), one block per node ----------------
__global__ void k_spmm(int buf) {
    const float* __restrict__ H = g_H[buf];
    int n = blockIdx.x, t = threadIdx.x;
    int beg = g_off[n], end = g_off[n + 1];
    float ai = 0.f, ao = 0.f;
    for (int j = beg; j < end; j++) {
        int sm = g_csr[j];
        float w = g_w[j];
        float v = __ldg(&H[(sm >> 1) * DD + t]);
        if (sm & 1) ai = fmaf(w, v, ai); else ao = fmaf(w, v, ao);
    }
    g_AGI[n * DD + t] = ai;
    g_AGO[n * DD + t] = ao;
}

// ---------------- fused dual GEMM: out = AGI@Wi + AGO@Wo + bi + bo ----------------
// Block tile 128(M) x 64(N), 256 threads, per-thread 8x4, K chunks of 8, two passes.
__global__ void k_gemm(const float* __restrict__ Wi, const float* __restrict__ Wo,
                       const float* __restrict__ bi, const float* __restrict__ bo,
                       int outbuf) {
    __shared__ float As[8][128];
    __shared__ float Bs[8][64];
    float* __restrict__ out = g_H[outbuf];
    int m0 = blockIdx.x * 128, n0 = blockIdx.y * 64;
    int tid = threadIdx.x;
    int tx = tid & 15, ty = tid >> 4;
    float acc[8][4];
#pragma unroll
    for (int i = 0; i < 8; i++)
#pragma unroll
        for (int j = 0; j < 4; j++) acc[i][j] = 0.f;

    for (int pass = 0; pass < 2; pass++) {
        const float* __restrict__ A = pass ? g_AGO : g_AGI;
        const float* __restrict__ W = pass ? Wo : Wi;
        for (int kk = 0; kk < DD; kk += 8) {
            int am = tid >> 1, ak = (tid & 1) * 4;
            float4 a4 = *(const float4*)(A + (size_t)(m0 + am) * DD + kk + ak);
            As[ak + 0][am] = a4.x;
            As[ak + 1][am] = a4.y;
            As[ak + 2][am] = a4.z;
            As[ak + 3][am] = a4.w;
            int bn = tid & 63, bk = (tid >> 6) * 2;
            Bs[bk + 0][bn] = W[(kk + bk + 0) * DD + n0 + bn];
            Bs[bk + 1][bn] = W[(kk + bk + 1) * DD + n0 + bn];
            __syncthreads();
#pragma unroll
            for (int k = 0; k < 8; k++) {
                float4 a0 = *(const float4*)&As[k][ty * 8];
                float4 a1 = *(const float4*)&As[k][ty * 8 + 4];
                float4 b0 = *(const float4*)&Bs[k][tx * 4];
                float a[8] = {a0.x, a0.y, a0.z, a0.w, a1.x, a1.y, a1.z, a1.w};
                float b[4] = {b0.x, b0.y, b0.z, b0.w};
#pragma unroll
                for (int i = 0; i < 8; i++)
#pragma unroll
                    for (int j = 0; j < 4; j++)
                        acc[i][j] = fmaf(a[i], b[j], acc[i][j]);
            }
            __syncthreads();
        }
    }
#pragma unroll
    for (int i = 0; i < 8; i++) {
        int m = m0 + ty * 8 + i;
#pragma unroll
        for (int j = 0; j < 4; j++) {
            int nn = n0 + tx * 4 + j;
            out[(size_t)m * DD + nn] = acc[i][j] + bi[nn] + bo[nn];
        }
    }
}

// ---------------- LayerNorm + ReLU in place ----------------
__global__ void k_lnrelu(int buf, const float* __restrict__ lg, const float* __restrict__ lb) {
    float* __restrict__ H = g_H[buf];
    int n = blockIdx.x, t = threadIdx.x;
    __shared__ float r1[256], r2[256];
    float v = H[n * DD + t];
    r1[t] = v; r2[t] = v * v;
    __syncthreads();
    for (int o = 128; o > 0; o >>= 1) {
        if (t < o) { r1[t] += r1[t + o]; r2[t] += r2[t + o]; }
        __syncthreads();
    }
    float m = r1[0] * (1.f / DD);
    float var = r2[0] * (1.f / DD) - m * m;
    float y = (v - m) * rsqrtf(var + 1e-5f) * lg[t] + lb[t];
    H[n * DD + t] = y > 0.f ? y : 0.f;
}

// ---------------- fragment pooling + LN + mask ----------------
__global__ void k_frag(int buf, const float* __restrict__ fg, const float* __restrict__ fb,
                       float* __restrict__ emb, float* __restrict__ fmask) {
    const float* __restrict__ H = g_H[buf];
    int b = blockIdx.x >> 4;
    int k = blockIdx.x & 15;
    int t = threadIdx.x;
    __shared__ float r1[256], r2[256];
    float acc = 0.f;
    int cnt = 0;
    int base = b * NPGX;
    for (int p = 0; p < NPGX; p++) {
        if (g_frag[base + p] == k) {
            acc += H[(base + p) * DD + t];
            cnt++;
        }
    }
    r1[t] = acc; r2[t] = acc * acc;
    __syncthreads();
    for (int o = 128; o > 0; o >>= 1) {
        if (t < o) { r1[t] += r1[t + o]; r2[t] += r2[t + o]; }
        __syncthreads();
    }
    float m = r1[0] * (1.f / DD);
    float var = r2[0] * (1.f / DD) - m * m;
    float y = (acc - m) * rsqrtf(var + 1e-5f) * fg[t] + fb[t];
    emb[(b * KF + k) * DD + t] = y;
    if (t == 0) fmask[b * KF + k] = (cnt > 0) ? 1.f : 0.f;
}

// ---------------- reg loss ----------------
__global__ void k_reg(const float* __restrict__ w0, const float* __restrict__ bo0,
                      const float* __restrict__ W, const float* __restrict__ bo,
                      float* __restrict__ out) {
    __shared__ float r[256];
    int t = threadIdx.x;
    float a = 0.f;
    for (int i = t; i < DIN * DD; i += 256) a += fabsf(w0[i]);
    a += fabsf(bo0[t]);
    for (int i = t; i < 3 * DD * DD; i += 256) a += fabsf(W[i]);
    for (int i = t; i < 3 * DD; i += 256) a += fabsf(bo[i]);
    r[t] = a;
    __syncthreads();
    for (int o = 128; o > 0; o >>= 1) {
        if (t < o) r[t] += r[t + o];
        __syncthreads();
    }
    if (t == 0) out[0] = r[0];
}

// ---------------- launch ----------------
extern "C" void kernel_launch(void* const* d_in, const int* in_sizes, int n_in,
                              void* d_out, int out_size) {
    const float* x   = (const float*)d_in[0];
    const int*   ei  = (const int*)d_in[1];
    const void*  msk = d_in[2];
    const float* s   = (const float*)d_in[3];
    // d_in[4] = batch (implicit: n/160)
    const float* Wi0 = (const float*)d_in[5];
    const float* Wo0 = (const float*)d_in[6];
    const float* bi0 = (const float*)d_in[7];
    const float* bo0 = (const float*)d_in[8];
    const float* Wi  = (const float*)d_in[9];
    const float* Wo  = (const float*)d_in[10];
    const float* bi  = (const float*)d_in[11];
    const float* bo  = (const float*)d_in[12];
    const float* lg  = (const float*)d_in[13];
    const float* lb  = (const float*)d_in[14];
    const float* fg  = (const float*)d_in[15];
    const float* fb  = (const float*)d_in[16];
    float* out = (float*)d_out;

    const int* src = ei;
    const int* dst = ei + NE;

    k_init<<<(NN + 255) / 256, 256>>>(s);
    k_deg<<<(NE + 255) / 256, 256>>>(dst);
    k_scan<<<1, 1024>>>((const unsigned char*)msk);
    k_csr<<<(NE + 255) / 256, 256>>>(src, dst, msk);

    k_spmm0<<<NN / 8, 256>>>(x);
    k_layer0<<<NN, 256>>>(Wi0, Wo0, bi0, bo0, lg, lb);

    int cur = 0;
    for (int l = 0; l < 3; l++) {
        k_spmm<<<NN, 256>>>(cur);
        k_gemm<<<dim3(NN / 128, DD / 64), 256>>>(Wi + l * DD * DD, Wo + l * DD * DD,
                                                 bi + l * DD, bo + l * DD, 1 - cur);
        k_lnrelu<<<NN, 256>>>(1 - cur, lg + (l + 1) * DD, lb + (l + 1) * DD);
        cur = 1 - cur;
    }

    k_frag<<<BBG * KF, 256>>>(cur, fg, fb, out, out + BBG * KF * DD);
    k_reg<<<1, 256>>>(Wo0, bo0, Wo, bo, out + BBG * KF * DD + BBG * KF);
}

// round 3
// speedup vs baseline: 2.2992x; 2.2992x over previous
#include <cuda_runtime.h>
#include <cuda_bf16.h>
#include <cstdint>

#define NN   10240
#define NE   320000
#define BBG  64
#define NPGX 160
#define KF   16
#define DIN  25
#define DD   256

#if defined(__CUDA_ARCH_FEAT_SM103_ALL) || defined(__CUDA_ARCH_FEAT_SM100_ALL)
#define USE_TCGEN05 1
#else
#define USE_TCGEN05 0
#endif

// ---------------- device scratch (static, allocation-free) ----------------
__device__ int   g_deg[NN];
__device__ int   g_off[NN + 1];
__device__ int   g_cur[NN];
__device__ float g_dinv[NN];
__device__ int   g_csr[NE];    // (src<<1) | mask
__device__ float g_w[NE];      // edge norm
__device__ int   g_frag[NN];
__device__ int   g_mask_is_int;
__device__ float g_H[2][NN * DD];
__device__ float g_AGI0[NN * 32];
__device__ float g_AGO0[NN * 32];
// bf16 split SpMM outputs: 0=AGI_hi 1=AGI_lo 2=AGO_hi 3=AGO_lo
__device__ __nv_bfloat16 g_Abf[4][NN * DD];
// packed transposed weights: [3 layers][6 segs][256 n][256 k] bf16
__device__ __nv_bfloat16 g_Wp[3 * 6 * DD * DD];

// ---------------- PTX helpers ----------------
__device__ __forceinline__ uint32_t smem_u32(const void* p) {
    uint32_t a;
    asm("{ .reg .u64 t; cvta.to.shared.u64 t, %1; cvt.u32.u64 %0, t; }" : "=r"(a) : "l"(p));
    return a;
}
#define SWZ128(b) ((b) ^ (((b) >> 3) & 0x70))

#if USE_TCGEN05
__device__ __forceinline__ uint32_t elect_one() {
    uint32_t p;
    asm volatile("{ .reg .pred p; elect.sync _|p, 0xFFFFFFFF; selp.b32 %0, 1, 0, p; }" : "=r"(p));
    return p;
}
#define MBAR_INIT(a, c) asm volatile("mbarrier.init.shared.b64 [%0], %1;" :: "r"(a), "r"(c) : "memory")
#define MBAR_WAIT(a, ph) do { \
    uint32_t _m = (a); uint32_t _p = (ph); uint32_t _d; \
    asm volatile("{ .reg .pred p; mbarrier.try_wait.parity.acquire.cta.shared::cta.b64 p, [%1], %2; selp.b32 %0,1,0,p; }" \
        : "=r"(_d) : "r"(_m), "r"(_p) : "memory"); \
    if (!_d) { \
        asm volatile("{ .reg .pred P1; WL_%=: mbarrier.try_wait.parity.acquire.cta.shared::cta.b64 P1, [%0], %1, 0x989680; @P1 bra.uni WD_%=; bra.uni WL_%=; WD_%=: }" \
            :: "r"(_m), "r"(_p) : "memory"); \
    } } while (0)

static constexpr uint64_t DESC_BASE =
    (uint64_t(2) << 61) | (uint64_t(1) << 46) | (uint64_t(64) << 32) | (uint64_t(1) << 16);
#define MK_DESC(addr) (DESC_BASE | ((uint64_t)((addr) >> 4) & 0x3FFF))

// idesc kind::f16: dtype=F32(1)<<4, atype=BF16(1)<<7, btype=BF16(1)<<10, N/8<<17, M/16<<24
static constexpr uint32_t IDESC = (1u << 4) | (1u << 7) | (1u << 10) | ((256u / 8) << 17) | ((128u / 16) << 24);

__device__ __forceinline__ void mma_f16_ss(uint32_t d, uint64_t ad, uint64_t bd, uint32_t idesc, bool acc) {
    uint32_t en = acc ? 1u : 0u, z = 0;
    asm volatile(
        "{ .reg .pred p; setp.ne.u32 p, %5, 0;\n\t"
        "tcgen05.mma.cta_group::1.kind::f16 [%0], %1, %2, %3, {%4, %4, %4, %4}, p; }"
        :: "r"(d), "l"(ad), "l"(bd), "r"(idesc), "r"(z), "r"(en) : "memory");
}
#endif

// ---------------- setup ----------------
__global__ void k_init(const float* __restrict__ s) {
    int n = blockIdx.x * blockDim.x + threadIdx.x;
    if (n >= NN) return;
    g_deg[n] = 0;
    g_cur[n] = 0;
    int f = 0;
#pragma unroll
    for (int k = 0; k < KF; k++)
        if (s[n * KF + k] > 0.5f) f = k;
    g_frag[n] = f;
}

__global__ void k_deg(const int* __restrict__ dst) {
    int e = blockIdx.x * blockDim.x + threadIdx.x;
    if (e < NE) atomicAdd(&g_deg[dst[e]], 1);
}

__global__ void k_scan(const unsigned char* __restrict__ maskb) {
    __shared__ int sh[1024];
    __shared__ int s_carry;
    __shared__ int s_flag;
    int t = threadIdx.x;
    if (t == 0) { s_carry = 0; s_flag = 0; }
    __syncthreads();
    {
        int idx = t * 4;
        int nz = (int)maskb[idx + 1] | (int)maskb[idx + 2] | (int)maskb[idx + 3];
        if (nz) atomicOr(&s_flag, 1);
    }
    __syncthreads();
    if (t == 0) g_mask_is_int = (s_flag == 0) ? 1 : 0;

    for (int c = 0; c < NN; c += 1024) {
        int v = g_deg[c + t];
        g_dinv[c + t] = rsqrtf((float)(v > 0 ? v : 1));
        sh[t] = v;
        __syncthreads();
        for (int o = 1; o < 1024; o <<= 1) {
            int add = (t >= o) ? sh[t - o] : 0;
            __syncthreads();
            sh[t] += add;
            __syncthreads();
        }
        g_off[c + t] = s_carry + sh[t] - v;
        __syncthreads();
        if (t == 0) s_carry += sh[1023];
        __syncthreads();
    }
    if (t == 0) g_off[NN] = s_carry;
}

__global__ void k_csr(const int* __restrict__ src, const int* __restrict__ dst,
                      const void* __restrict__ maskp) {
    int e = blockIdx.x * blockDim.x + threadIdx.x;
    if (e >= NE) return;
    int u = src[e], v = dst[e];
    int mb;
    if (g_mask_is_int) mb = (((const int*)maskp)[e] != 0) ? 1 : 0;
    else               mb = (((const unsigned char*)maskp)[e] != 0) ? 1 : 0;
    int p = g_off[v] + atomicAdd(&g_cur[v], 1);
    g_csr[p] = (u << 1) | mb;
    g_w[p]   = g_dinv[u] * g_dinv[v];
}

// weight prep: transpose + bf16 split into 6 K-segments per layer
// seg order (A pairing): 0:Wi_hi(AGI_hi) 1:Wi_lo(AGI_hi) 2:Wi_hi(AGI_lo)
//                        3:Wo_hi(AGO_hi) 4:Wo_lo(AGO_hi) 5:Wo_hi(AGO_lo)
__global__ void k_wprep(const float* __restrict__ Wi, const float* __restrict__ Wo) {
    int idx = blockIdx.x * blockDim.x + threadIdx.x;   // over 3*256*256
    if (idx >= 3 * DD * DD) return;
    int l = idx / (DD * DD);
    int r = idx - l * DD * DD;
    int k = r / DD;
    int n = r - k * DD;
    float wi = Wi[idx], wo = Wo[idx];
    __nv_bfloat16 wih = __float2bfloat16(wi);
    __nv_bfloat16 wil = __float2bfloat16(wi - __bfloat162float(wih));
    __nv_bfloat16 woh = __float2bfloat16(wo);
    __nv_bfloat16 wol = __float2bfloat16(wo - __bfloat162float(woh));
    size_t base = (size_t)l * 6 * DD * DD + (size_t)n * DD + k;
    g_Wp[base + 0 * DD * DD] = wih;
    g_Wp[base + 1 * DD * DD] = wil;
    g_Wp[base + 2 * DD * DD] = wih;
    g_Wp[base + 3 * DD * DD] = woh;
    g_Wp[base + 4 * DD * DD] = wol;
    g_Wp[base + 5 * DD * DD] = woh;
}

// ---------------- layer 0: SpMM on 25-dim input ----------------
__global__ void k_spmm0(const float* __restrict__ x) {
    int warp = threadIdx.x >> 5;
    int lane = threadIdx.x & 31;
    int n = blockIdx.x * 8 + warp;
    if (n >= NN) return;
    int beg = g_off[n], end = g_off[n + 1];
    float ai = 0.f, ao = 0.f;
    for (int j = beg; j < end; j++) {
        int sm = g_csr[j];
        float w = g_w[j];
        float v = 0.f;
        if (lane < DIN) v = x[(sm >> 1) * DIN + lane];
        if (sm & 1) ai = fmaf(w, v, ai); else ao = fmaf(w, v, ao);
    }
    if (lane < DIN) {
        g_AGI0[n * 32 + lane] = ai;
        g_AGO0[n * 32 + lane] = ao;
    }
}

// layer 0 GEMM (K=25+25) fused with bias + LN + ReLU -> g_H[0]
__global__ void k_layer0(const float* __restrict__ Wi, const float* __restrict__ Wo,
                         const float* __restrict__ bi, const float* __restrict__ bo,
                         const float* __restrict__ lg, const float* __restrict__ lb) {
    int n = blockIdx.x, t = threadIdx.x;
    __shared__ float sai[DIN], sao[DIN];
    __shared__ float r1[256], r2[256];
    if (t < DIN) { sai[t] = g_AGI0[n * 32 + t]; sao[t] = g_AGO0[n * 32 + t]; }
    __syncthreads();
    float acc = bi[t] + bo[t];
#pragma unroll
    for (int j = 0; j < DIN; j++)
        acc += sai[j] * Wi[j * DD + t] + sao[j] * Wo[j * DD + t];
    r1[t] = acc; r2[t] = acc * acc;
    __syncthreads();
    for (int o = 128; o > 0; o >>= 1) {
        if (t < o) { r1[t] += r1[t + o]; r2[t] += r2[t + o]; }
        __syncthreads();
    }
    float m = r1[0] * (1.f / DD);
    float var = r2[0] * (1.f / DD) - m * m;
    float y = (acc - m) * rsqrtf(var + 1e-5f) * lg[t] + lb[t];
    g_H[0][n * DD + t] = y > 0.f ? y : 0.f;
}

// ---------------- per-layer SpMM (D=256) -> bf16 hi/lo splits ----------------
__global__ void k_spmm(int buf) {
    const float* __restrict__ H = g_H[buf];
    int n = blockIdx.x, t = threadIdx.x;
    int beg = g_off[n], end = g_off[n + 1];
    float ai = 0.f, ao = 0.f;
    for (int j = beg; j < end; j++) {
        int sm = g_csr[j];
        float w = g_w[j];
        float v = __ldg(&H[(sm >> 1) * DD + t]);
        if (sm & 1) ai = fmaf(w, v, ai); else ao = fmaf(w, v, ao);
    }
    int o = n * DD + t;
    __nv_bfloat16 h = __float2bfloat16(ai);
    g_Abf[0][o] = h;
    g_Abf[1][o] = __float2bfloat16(ai - __bfloat162float(h));
    h = __float2bfloat16(ao);
    g_Abf[2][o] = h;
    g_Abf[3][o] = __float2bfloat16(ao - __bfloat162float(h));
}

// ---------------- GEMM: 6-segment compensated dual GEMM, bias+LN+ReLU fused --
// One kernel symbol, two compile-time paths:
//   sm_103a image: tcgen05 bf16 SS MMA (SW128, double-buffered, TMEM epilogue)
//   sm_103 image : mma.sync.m16n8k16 bf16 HMMA fallback (padded smem rows)
// Tile M=128 (grid 80), N=256, K chunks of 64.
#define PAD_STRIDE 144
#define FA_BYTES  (128 * PAD_STRIDE)
#define FB_BYTES  (256 * PAD_STRIDE)
#define SMEM_NEED (1024 + 1024 + 2 * FA_BYTES + 2 * FB_BYTES)

__global__ __launch_bounds__(256, 1) void k_gemm_tc(
    const __nv_bfloat16* __restrict__ Wp,   // g_Wp + l*6*DD*DD
    const float* __restrict__ bi, const float* __restrict__ bo,
    const float* __restrict__ lg, const float* __restrict__ lb,
    int outbuf)
{
    extern __shared__ char smem[];
    uint32_t raw = smem_u32(smem);
    uint32_t sb = (raw + 1023u) & ~1023u;   // 1024-aligned base
    char* smp = smem + (sb - raw);
    int tid = threadIdx.x;
    int wid = tid >> 5, lid = tid & 31;
    int m0 = blockIdx.x * 128;
    const int segA[6] = {0, 0, 1, 2, 2, 3};

#if USE_TCGEN05
    // ---------------- tcgen05 path ----------------
    const uint32_t aoff[2] = {1024u, 1024u + 128 * 128};
    const uint32_t boff[2] = {1024u + 2 * 128 * 128, 1024u + 2 * 128 * 128 + 256 * 128};

    if (wid == 0) {
        asm volatile("tcgen05.alloc.cta_group::1.sync.aligned.shared::cta.b32 [%0], %1;"
                     :: "r"(sb), "r"(512u) : "memory");
    }
    if (tid == 0) { MBAR_INIT(sb + 8, 1); MBAR_INIT(sb + 16, 1); }
    __syncthreads();
    uint32_t tmem;
    asm volatile("ld.shared.b32 %0, [%1];" : "=r"(tmem) : "r"(sb));

    int ph0 = 0, ph1 = 0;
    int chunk = 0;
    for (int s = 0; s < 6; s++) {
        const __nv_bfloat16* __restrict__ Ag = g_Abf[segA[s]];
        const __nv_bfloat16* __restrict__ Bg = Wp + (size_t)s * DD * DD;
        for (int c = 0; c < 4; c++) {
            int buf = chunk & 1;
            if (chunk >= 2) {
                if (buf == 0) { MBAR_WAIT(sb + 8, ph0); ph0 ^= 1; }
                else          { MBAR_WAIT(sb + 16, ph1); ph1 ^= 1; }
            }
            int kc = c * 64;
#pragma unroll
            for (int u = 0; u < 4; u++) {
                int idx = u * 256 + tid;
                int row = idx >> 3, q = idx & 7;
                uint4 v = *(const uint4*)(Ag + (size_t)(m0 + row) * DD + kc + q * 8);
                *(uint4*)(smp + aoff[buf] + SWZ128(row * 128 + q * 16)) = v;
            }
#pragma unroll
            for (int u = 0; u < 8; u++) {
                int idx = u * 256 + tid;
                int row = idx >> 3, q = idx & 7;
                uint4 v = *(const uint4*)(Bg + (size_t)row * DD + kc + q * 8);
                *(uint4*)(smp + boff[buf] + SWZ128(row * 128 + q * 16)) = v;
            }
            __syncthreads();
            if (wid == 0) {
                asm volatile("fence.proxy.async.shared::cta;" ::: "memory");
                if (elect_one()) {
                    uint64_t ad = MK_DESC(sb + aoff[buf]);
                    uint64_t bd = MK_DESC(sb + boff[buf]);
#pragma unroll
                    for (int st = 0; st < 4; st++)
                        mma_f16_ss(tmem, ad + st * 2, bd + st * 2, IDESC, !(chunk == 0 && st == 0));
                    asm volatile(
                        "tcgen05.commit.cta_group::1.mbarrier::arrive::one.shared::cluster.b64 [%0];"
                        :: "r"(sb + 8 + buf * 8) : "memory");
                }
            }
            __syncthreads();
            chunk++;
        }
    }
    MBAR_WAIT(sb + 8, ph0);
    MBAR_WAIT(sb + 16, ph1);
    asm volatile("tcgen05.fence::after_thread_sync;" ::: "memory");
    __syncthreads();

    if (wid < 4) {
        int row = m0 + wid * 32 + lid;
        float sum = 0.f, sq = 0.f;
        uint32_t r[32];
        for (int cb = 0; cb < 8; cb++) {
            asm volatile(
                "tcgen05.ld.sync.aligned.32x32b.x32.b32 "
                "{%0,%1,%2,%3,%4,%5,%6,%7,%8,%9,%10,%11,%12,%13,%14,%15,"
                "%16,%17,%18,%19,%20,%21,%22,%23,%24,%25,%26,%27,%28,%29,%30,%31}, [%32];"
                : "=r"(r[0]), "=r"(r[1]), "=r"(r[2]), "=r"(r[3]), "=r"(r[4]), "=r"(r[5]), "=r"(r[6]), "=r"(r[7]),
                  "=r"(r[8]), "=r"(r[9]), "=r"(r[10]), "=r"(r[11]), "=r"(r[12]), "=r"(r[13]), "=r"(r[14]), "=r"(r[15]),
                  "=r"(r[16]), "=r"(r[17]), "=r"(r[18]), "=r"(r[19]), "=r"(r[20]), "=r"(r[21]), "=r"(r[22]), "=r"(r[23]),
                  "=r"(r[24]), "=r"(r[25]), "=r"(r[26]), "=r"(r[27]), "=r"(r[28]), "=r"(r[29]), "=r"(r[30]), "=r"(r[31])
                : "r"(tmem + cb * 32));
            asm volatile("tcgen05.wait::ld.sync.aligned;" ::: "memory");
#pragma unroll
            for (int j = 0; j < 32; j++) {
                int nn = cb * 32 + j;
                float v = __uint_as_float(r[j]) + __ldg(&bi[nn]) + __ldg(&bo[nn]);
                sum += v; sq += v * v;
            }
        }
        float mean = sum * (1.f / DD);
        float var = sq * (1.f / DD) - mean * mean;
        float rstd = rsqrtf(var + 1e-5f);
        float* __restrict__ Hout = g_H[outbuf];
        for (int cb = 0; cb < 8; cb++) {
            asm volatile(
                "tcgen05.ld.sync.aligned.32x32b.x32.b32 "
                "{%0,%1,%2,%3,%4,%5,%6,%7,%8,%9,%10,%11,%12,%13,%14,%15,"
                "%16,%17,%18,%19,%20,%21,%22,%23,%24,%25,%26,%27,%28,%29,%30,%31}, [%32];"
                : "=r"(r[0]), "=r"(r[1]), "=r"(r[2]), "=r"(r[3]), "=r"(r[4]), "=r"(r[5]), "=r"(r[6]), "=r"(r[7]),
                  "=r"(r[8]), "=r"(r[9]), "=r"(r[10]), "=r"(r[11]), "=r"(r[12]), "=r"(r[13]), "=r"(r[14]), "=r"(r[15]),
                  "=r"(r[16]), "=r"(r[17]), "=r"(r[18]), "=r"(r[19]), "=r"(r[20]), "=r"(r[21]), "=r"(r[22]), "=r"(r[23]),
                  "=r"(r[24]), "=r"(r[25]), "=r"(r[26]), "=r"(r[27]), "=r"(r[28]), "=r"(r[29]), "=r"(r[30]), "=r"(r[31])
                : "r"(tmem + cb * 32));
            asm volatile("tcgen05.wait::ld.sync.aligned;" ::: "memory");
#pragma unroll
            for (int j = 0; j < 32; j++) {
                int nn = cb * 32 + j;
                float v = __uint_as_float(r[j]) + __ldg(&bi[nn]) + __ldg(&bo[nn]);
                float y = (v - mean) * rstd * __ldg(&lg[nn]) + __ldg(&lb[nn]);
                Hout[(size_t)row * DD + nn] = y > 0.f ? y : 0.f;
            }
        }
    }
    __syncthreads();
    if (wid == 0) {
        asm volatile("tcgen05.relinquish_alloc_permit.cta_group::1.sync.aligned;");
        asm volatile("tcgen05.dealloc.cta_group::1.sync.aligned.b32 %0, %1;" :: "r"(tmem), "r"(512u));
    }
#else
    // ---------------- mma.sync bf16 fallback path (plain sm_103) ----------------
    __shared__ float sdsum[128];
    __shared__ float sdsq[128];
    const uint32_t aoff[2] = {1024u, 1024u + FA_BYTES};
    const uint32_t boff[2] = {1024u + 2 * FA_BYTES, 1024u + 2 * FA_BYTES + FB_BYTES};
    int gid = lid >> 2, t4 = lid & 3;
    int wm = wid >> 1, wn = wid & 1;
    int mrow = wm * 32, ncol = wn * 128;
    float acc[2][16][4];
#pragma unroll
    for (int i = 0; i < 2; i++)
#pragma unroll
        for (int j = 0; j < 16; j++)
#pragma unroll
            for (int q = 0; q < 4; q++) acc[i][j][q] = 0.f;

    int chunk = 0;
    for (int s = 0; s < 6; s++) {
        const __nv_bfloat16* __restrict__ Ag = g_Abf[segA[s]];
        const __nv_bfloat16* __restrict__ Bg = Wp + (size_t)s * DD * DD;
        for (int c = 0; c < 4; c++) {
            int buf = chunk & 1;
            int kc = c * 64;
            __syncthreads();
#pragma unroll
            for (int u = 0; u < 4; u++) {
                int idx = u * 256 + tid;
                int row = idx >> 3, q = idx & 7;
                uint4 v = *(const uint4*)(Ag + (size_t)(m0 + row) * DD + kc + q * 8);
                *(uint4*)(smp + aoff[buf] + row * PAD_STRIDE + q * 16) = v;
            }
#pragma unroll
            for (int u = 0; u < 8; u++) {
                int idx = u * 256 + tid;
                int row = idx >> 3, q = idx & 7;
                uint4 v = *(const uint4*)(Bg + (size_t)row * DD + kc + q * 8);
                *(uint4*)(smp + boff[buf] + row * PAD_STRIDE + q * 16) = v;
            }
            __syncthreads();
            const char* ab = smp + aoff[buf];
            const char* bb = smp + boff[buf];
#pragma unroll
            for (int ks = 0; ks < 4; ks++) {
                int kb = ks * 32;   // byte offset: k*2, k = ks*16
                uint32_t a[2][4];
#pragma unroll
                for (int ma = 0; ma < 2; ma++) {
                    int r0 = mrow + ma * 16 + gid;
                    a[ma][0] = *(const uint32_t*)(ab + r0 * PAD_STRIDE + kb + t4 * 4);
                    a[ma][1] = *(const uint32_t*)(ab + (r0 + 8) * PAD_STRIDE + kb + t4 * 4);
                    a[ma][2] = *(const uint32_t*)(ab + r0 * PAD_STRIDE + kb + 16 + t4 * 4);
                    a[ma][3] = *(const uint32_t*)(ab + (r0 + 8) * PAD_STRIDE + kb + 16 + t4 * 4);
                }
#pragma unroll
                for (int nb = 0; nb < 16; nb++) {
                    int cc = ncol + nb * 8 + gid;
                    uint32_t b0 = *(const uint32_t*)(bb + cc * PAD_STRIDE + kb + t4 * 4);
                    uint32_t b1 = *(const uint32_t*)(bb + cc * PAD_STRIDE + kb + 16 + t4 * 4);
#pragma unroll
                    for (int ma = 0; ma < 2; ma++) {
                        asm volatile(
                            "mma.sync.aligned.m16n8k16.row.col.f32.bf16.bf16.f32 "
                            "{%0,%1,%2,%3}, {%4,%5,%6,%7}, {%8,%9}, {%0,%1,%2,%3};"
                            : "+f"(acc[ma][nb][0]), "+f"(acc[ma][nb][1]),
                              "+f"(acc[ma][nb][2]), "+f"(acc[ma][nb][3])
                            : "r"(a[ma][0]), "r"(a[ma][1]), "r"(a[ma][2]), "r"(a[ma][3]),
                              "r"(b0), "r"(b1));
                    }
                }
            }
            chunk++;
        }
    }
    __syncthreads();
    if (tid < 128) { sdsum[tid] = 0.f; sdsq[tid] = 0.f; }
    __syncthreads();
    float* __restrict__ Hout = g_H[outbuf];
#pragma unroll
    for (int ma = 0; ma < 2; ma++) {
#pragma unroll
        for (int nb = 0; nb < 16; nb++) {
#pragma unroll
            for (int q = 0; q < 4; q++) {
                int row = mrow + ma * 16 + gid + ((q >= 2) ? 8 : 0);
                int col = ncol + nb * 8 + t4 * 2 + (q & 1);
                float v = acc[ma][nb][q] + __ldg(&bi[col]) + __ldg(&bo[col]);
                Hout[(size_t)(m0 + row) * DD + col] = v;
                atomicAdd(&sdsum[row], v);
                atomicAdd(&sdsq[row], v * v);
            }
        }
    }
    __syncthreads();
    for (int r = wid; r < 128; r += 8) {
        float mean = sdsum[r] * (1.f / DD);
        float var = sdsq[r] * (1.f / DD) - mean * mean;
        float rstd = rsqrtf(var + 1e-5f);
#pragma unroll
        for (int u = 0; u < 8; u++) {
            int col = u * 32 + lid;
            float v = Hout[(size_t)(m0 + r) * DD + col];
            float y = (v - mean) * rstd * __ldg(&lg[col]) + __ldg(&lb[col]);
            Hout[(size_t)(m0 + r) * DD + col] = y > 0.f ? y : 0.f;
        }
    }
#endif
}

// ---------------- fragment pooling + LN + mask ----------------
__global__ void k_frag(int buf, const float* __restrict__ fg, const float* __restrict__ fb,
                       float* __restrict__ emb, float* __restrict__ fmask) {
    const float* __restrict__ H = g_H[buf];
    int b = blockIdx.x >> 4;
    int k = blockIdx.x & 15;
    int t = threadIdx.x;
    __shared__ float r1[256], r2[256];
    float acc = 0.f;
    int cnt = 0;
    int base = b * NPGX;
    for (int p = 0; p < NPGX; p++) {
        if (g_frag[base + p] == k) {
            acc += H[(base + p) * DD + t];
            cnt++;
        }
    }
    r1[t] = acc; r2[t] = acc * acc;
    __syncthreads();
    for (int o = 128; o > 0; o >>= 1) {
        if (t < o) { r1[t] += r1[t + o]; r2[t] += r2[t + o]; }
        __syncthreads();
    }
    float m = r1[0] * (1.f / DD);
    float var = r2[0] * (1.f / DD) - m * m;
    float y = (acc - m) * rsqrtf(var + 1e-5f) * fg[t] + fb[t];
    emb[(b * KF + k) * DD + t] = y;
    if (t == 0) fmask[b * KF + k] = (cnt > 0) ? 1.f : 0.f;
}

// ---------------- reg loss ----------------
__global__ void k_reg(const float* __restrict__ w0, const float* __restrict__ bo0,
                      const float* __restrict__ W, const float* __restrict__ bo,
                      float* __restrict__ out) {
    __shared__ float r[256];
    int t = threadIdx.x;
    float a = 0.f;
    for (int i = t; i < DIN * DD; i += 256) a += fabsf(w0[i]);
    a += fabsf(bo0[t]);
    for (int i = t; i < 3 * DD * DD; i += 256) a += fabsf(W[i]);
    for (int i = t; i < 3 * DD; i += 256) a += fabsf(bo[i]);
    r[t] = a;
    __syncthreads();
    for (int o = 128; o > 0; o >>= 1) {
        if (t < o) r[t] += r[t + o];
        __syncthreads();
    }
    if (t == 0) out[0] = r[0];
}

// ---------------- launch ----------------
extern "C" void kernel_launch(void* const* d_in, const int* in_sizes, int n_in,
                              void* d_out, int out_size) {
    const float* x   = (const float*)d_in[0];
    const int*   ei  = (const int*)d_in[1];
    const void*  msk = d_in[2];
    const float* s   = (const float*)d_in[3];
    const float* Wi0 = (const float*)d_in[5];
    const float* Wo0 = (const float*)d_in[6];
    const float* bi0 = (const float*)d_in[7];
    const float* bo0 = (const float*)d_in[8];
    const float* Wi  = (const float*)d_in[9];
    const float* Wo  = (const float*)d_in[10];
    const float* bi  = (const float*)d_in[11];
    const float* bo  = (const float*)d_in[12];
    const float* lg  = (const float*)d_in[13];
    const float* lb  = (const float*)d_in[14];
    const float* fg  = (const float*)d_in[15];
    const float* fb  = (const float*)d_in[16];
    float* out = (float*)d_out;

    const int* src = ei;
    const int* dst = ei + NE;

    cudaFuncSetAttribute(k_gemm_tc, cudaFuncAttributeMaxDynamicSharedMemorySize, SMEM_NEED);

    k_init<<<(NN + 255) / 256, 256>>>(s);
    k_deg<<<(NE + 255) / 256, 256>>>(dst);
    k_scan<<<1, 1024>>>((const unsigned char*)msk);
    k_csr<<<(NE + 255) / 256, 256>>>(src, dst, msk);
    k_wprep<<<(3 * DD * DD + 255) / 256, 256>>>(Wi, Wo);

    k_spmm0<<<NN / 8, 256>>>(x);
    k_layer0<<<NN, 256>>>(Wi0, Wo0, bi0, bo0, lg, lb);

    __nv_bfloat16* wp_dev = nullptr;
    cudaGetSymbolAddress((void**)&wp_dev, g_Wp);

    int cur = 0;
    for (int l = 0; l < 3; l++) {
        k_spmm<<<NN, 256>>>(cur);
        k_gemm_tc<<<NN / 128, 256, SMEM_NEED>>>(wp_dev + (size_t)l * 6 * DD * DD,
                                                bi + l * DD, bo + l * DD,
                                                lg + (l + 1) * DD, lb + (l + 1) * DD, 1 - cur);
        cur = 1 - cur;
    }

    k_frag<<<BBG * KF, 256>>>(cur, fg, fb, out, out + BBG * KF * DD);
    k_reg<<<1, 256>>>(Wo0, bo0, Wo, bo, out + BBG * KF * DD + BBG * KF);
}

// round 4
// speedup vs baseline: 2.5566x; 1.1120x over previous
#include <cuda_runtime.h>
#include <cuda_bf16.h>
#include <cstdint>

#define NN   10240
#define NE   320000
#define BBG  64
#define NPGX 160
#define KF   16
#define DIN  25
#define DD   256

#if defined(__CUDA_ARCH_FEAT_SM103_ALL) || defined(__CUDA_ARCH_FEAT_SM100_ALL)
#define USE_TCGEN05 1
#else
#define USE_TCGEN05 0
#endif

// ---------------- device scratch (static, allocation-free) ----------------
__device__ int   g_deg[NN];
__device__ int   g_off[NN + 1];
__device__ int   g_cur[NN];
__device__ float g_dinv[NN];
__device__ int2  g_csrw[NE];   // {(src<<1)|mask, bitcast(norm)}
__device__ int   g_frag[NN];
__device__ int   g_mask_is_int;
__device__ float g_H[2][NN * DD];
__device__ float g_AGI0[NN * 32];
__device__ float g_AGO0[NN * 32];
// bf16 split SpMM outputs: 0=AGI_hi 1=AGI_lo 2=AGO_hi 3=AGO_lo
__device__ __nv_bfloat16 g_Abf[4][NN * DD];
// packed transposed weights: [3 layers][6 segs][256 n][256 k] bf16
__device__ __nv_bfloat16 g_Wp[3 * 6 * DD * DD];

// ---------------- PTX helpers ----------------
__device__ __forceinline__ uint32_t smem_u32(const void* p) {
    uint32_t a;
    asm("{ .reg .u64 t; cvta.to.shared.u64 t, %1; cvt.u32.u64 %0, t; }" : "=r"(a) : "l"(p));
    return a;
}
#define SWZ128(b) ((b) ^ (((b) >> 3) & 0x70))
#define CP_ASYNC16(dst, src) \
    asm volatile("cp.async.cg.shared.global [%0], [%1], 16;" :: "r"(dst), "l"(src) : "memory")
#define CP_COMMIT  asm volatile("cp.async.commit_group;" ::: "memory")
#define CP_WAIT0   asm volatile("cp.async.wait_group 0;" ::: "memory")

#if USE_TCGEN05
__device__ __forceinline__ uint32_t elect_one() {
    uint32_t p;
    asm volatile("{ .reg .pred p; elect.sync _|p, 0xFFFFFFFF; selp.b32 %0, 1, 0, p; }" : "=r"(p));
    return p;
}
#define MBAR_INIT(a, c) asm volatile("mbarrier.init.shared.b64 [%0], %1;" :: "r"(a), "r"(c) : "memory")
#define MBAR_WAIT(a, ph) do { \
    uint32_t _m = (a); uint32_t _p = (ph); uint32_t _d; \
    asm volatile("{ .reg .pred p; mbarrier.try_wait.parity.acquire.cta.shared::cta.b64 p, [%1], %2; selp.b32 %0,1,0,p; }" \
        : "=r"(_d) : "r"(_m), "r"(_p) : "memory"); \
    if (!_d) { \
        asm volatile("{ .reg .pred P1; WL_%=: mbarrier.try_wait.parity.acquire.cta.shared::cta.b64 P1, [%0], %1, 0x989680; @P1 bra.uni WD_%=; bra.uni WL_%=; WD_%=: }" \
            :: "r"(_m), "r"(_p) : "memory"); \
    } } while (0)

static constexpr uint64_t DESC_BASE =
    (uint64_t(2) << 61) | (uint64_t(1) << 46) | (uint64_t(64) << 32) | (uint64_t(1) << 16);
#define MK_DESC(addr) (DESC_BASE | ((uint64_t)((addr) >> 4) & 0x3FFF))

// idesc kind::f16: dtype=F32(1)<<4, atype=BF16(1)<<7, btype=BF16(1)<<10, N/8<<17, M/16<<24
static constexpr uint32_t IDESC = (1u << 4) | (1u << 7) | (1u << 10) | ((256u / 8) << 17) | ((128u / 16) << 24);

__device__ __forceinline__ void mma_f16_ss(uint32_t d, uint64_t ad, uint64_t bd, uint32_t idesc, bool acc) {
    uint32_t en = acc ? 1u : 0u, z = 0;
    asm volatile(
        "{ .reg .pred p; setp.ne.u32 p, %5, 0;\n\t"
        "tcgen05.mma.cta_group::1.kind::f16 [%0], %1, %2, %3, {%4, %4, %4, %4}, p; }"
        :: "r"(d), "l"(ad), "l"(bd), "r"(idesc), "r"(z), "r"(en) : "memory");
}
#endif

// ---------------- setup ----------------
__global__ void k_init(const float* __restrict__ s) {
    int n = blockIdx.x * blockDim.x + threadIdx.x;
    if (n >= NN) return;
    g_deg[n] = 0;
    g_cur[n] = 0;
    int f = 0;
#pragma unroll
    for (int k = 0; k < KF; k++)
        if (s[n * KF + k] > 0.5f) f = k;
    g_frag[n] = f;
}

__global__ void k_deg(const int* __restrict__ dst) {
    int e = blockIdx.x * blockDim.x + threadIdx.x;
    if (e < NE) atomicAdd(&g_deg[dst[e]], 1);
}

// Single-block single-pass scan: 1024 threads x 10 elements each, shuffle-based.
__global__ void k_scan(const unsigned char* __restrict__ maskb) {
    __shared__ int warp_tot[32];
    __shared__ int warp_pre[32];
    __shared__ int s_flag;
    int t = threadIdx.x;
    int lane = t & 31, wd = t >> 5;
    if (t == 0) s_flag = 0;
    __syncthreads();
    {
        int idx = t * 4;
        int nz = (int)maskb[idx + 1] | (int)maskb[idx + 2] | (int)maskb[idx + 3];
        if (__syncthreads_or(nz)) { if (t == 0) g_mask_is_int = 0; }
        else                      { if (t == 0) g_mask_is_int = 1; }
    }
    int base = t * 10;
    int loc[10];
    int tot = 0;
#pragma unroll
    for (int i = 0; i < 10; i++) {
        int v = g_deg[base + i];
        g_dinv[base + i] = rsqrtf((float)(v > 0 ? v : 1));
        loc[i] = tot;
        tot += v;
    }
    int inc = tot;
#pragma unroll
    for (int o = 1; o < 32; o <<= 1) {
        int nv = __shfl_up_sync(0xFFFFFFFFu, inc, o);
        if (lane >= o) inc += nv;
    }
    if (lane == 31) warp_tot[wd] = inc;
    __syncthreads();
    if (wd == 0) {
        int v = warp_tot[lane];
        int iv = v;
#pragma unroll
        for (int o = 1; o < 32; o <<= 1) {
            int nv = __shfl_up_sync(0xFFFFFFFFu, iv, o);
            if (lane >= o) iv += nv;
        }
        warp_pre[lane] = iv - v;
    }
    __syncthreads();
    int texcl = inc - tot + warp_pre[wd];
#pragma unroll
    for (int i = 0; i < 10; i++)
        g_off[base + i] = texcl + loc[i];
    if (t == 1023) g_off[NN] = texcl + tot;
}

__global__ void k_csr(const int* __restrict__ src, const int* __restrict__ dst,
                      const void* __restrict__ maskp) {
    int e = blockIdx.x * blockDim.x + threadIdx.x;
    if (e >= NE) return;
    int u = src[e], v = dst[e];
    int mb;
    if (g_mask_is_int) mb = (((const int*)maskp)[e] != 0) ? 1 : 0;
    else               mb = (((const unsigned char*)maskp)[e] != 0) ? 1 : 0;
    int p = g_off[v] + atomicAdd(&g_cur[v], 1);
    g_csrw[p] = make_int2((u << 1) | mb, __float_as_int(g_dinv[u] * g_dinv[v]));
}

// weight prep: transpose + bf16 split into 6 K-segments per layer
__global__ void k_wprep(const float* __restrict__ Wi, const float* __restrict__ Wo) {
    int idx = blockIdx.x * blockDim.x + threadIdx.x;   // over 3*256*256
    if (idx >= 3 * DD * DD) return;
    int l = idx / (DD * DD);
    int r = idx - l * DD * DD;
    int k = r / DD;
    int n = r - k * DD;
    float wi = Wi[idx], wo = Wo[idx];
    __nv_bfloat16 wih = __float2bfloat16(wi);
    __nv_bfloat16 wil = __float2bfloat16(wi - __bfloat162float(wih));
    __nv_bfloat16 woh = __float2bfloat16(wo);
    __nv_bfloat16 wol = __float2bfloat16(wo - __bfloat162float(woh));
    size_t base = (size_t)l * 6 * DD * DD + (size_t)n * DD + k;
    g_Wp[base + 0 * DD * DD] = wih;
    g_Wp[base + 1 * DD * DD] = wil;
    g_Wp[base + 2 * DD * DD] = wih;
    g_Wp[base + 3 * DD * DD] = woh;
    g_Wp[base + 4 * DD * DD] = wol;
    g_Wp[base + 5 * DD * DD] = woh;
}

// ---------------- layer 0: SpMM on 25-dim input ----------------
__global__ void k_spmm0(const float* __restrict__ x) {
    int warp = threadIdx.x >> 5;
    int lane = threadIdx.x & 31;
    int n = blockIdx.x * 8 + warp;
    if (n >= NN) return;
    int beg = g_off[n], end = g_off[n + 1];
    float ai = 0.f, ao = 0.f;
    int j = beg;
    for (; j + 2 <= end; j += 2) {
        int2 e0 = g_csrw[j], e1 = g_csrw[j + 1];
        float v0 = 0.f, v1 = 0.f;
        if (lane < DIN) {
            v0 = x[(e0.x >> 1) * DIN + lane];
            v1 = x[(e1.x >> 1) * DIN + lane];
        }
        float w0 = __int_as_float(e0.y), w1 = __int_as_float(e1.y);
        if (e0.x & 1) ai = fmaf(w0, v0, ai); else ao = fmaf(w0, v0, ao);
        if (e1.x & 1) ai = fmaf(w1, v1, ai); else ao = fmaf(w1, v1, ao);
    }
    for (; j < end; j++) {
        int2 e0 = g_csrw[j];
        float v0 = (lane < DIN) ? x[(e0.x >> 1) * DIN + lane] : 0.f;
        float w0 = __int_as_float(e0.y);
        if (e0.x & 1) ai = fmaf(w0, v0, ai); else ao = fmaf(w0, v0, ao);
    }
    if (lane < DIN) {
        g_AGI0[n * 32 + lane] = ai;
        g_AGO0[n * 32 + lane] = ao;
    }
}

// layer 0 GEMM (K=25+25) fused with bias + LN + ReLU -> g_H[0]
__global__ void k_layer0(const float* __restrict__ Wi, const float* __restrict__ Wo,
                         const float* __restrict__ bi, const float* __restrict__ bo,
                         const float* __restrict__ lg, const float* __restrict__ lb) {
    int n = blockIdx.x, t = threadIdx.x;
    int lane = t & 31, wd = t >> 5;
    __shared__ float sai[DIN], sao[DIN];
    __shared__ float w1[8], w2[8];
    if (t < DIN) { sai[t] = g_AGI0[n * 32 + t]; sao[t] = g_AGO0[n * 32 + t]; }
    __syncthreads();
    float acc = bi[t] + bo[t];
#pragma unroll
    for (int j = 0; j < DIN; j++)
        acc += sai[j] * Wi[j * DD + t] + sao[j] * Wo[j * DD + t];
    float s1 = acc, s2 = acc * acc;
#pragma unroll
    for (int o = 16; o > 0; o >>= 1) {
        s1 += __shfl_xor_sync(0xFFFFFFFFu, s1, o);
        s2 += __shfl_xor_sync(0xFFFFFFFFu, s2, o);
    }
    if (lane == 0) { w1[wd] = s1; w2[wd] = s2; }
    __syncthreads();
    float t1 = 0.f, t2 = 0.f;
#pragma unroll
    for (int i = 0; i < 8; i++) { t1 += w1[i]; t2 += w2[i]; }
    float m = t1 * (1.f / DD);
    float var = t2 * (1.f / DD) - m * m;
    float y = (acc - m) * rsqrtf(var + 1e-5f) * lg[t] + lb[t];
    g_H[0][n * DD + t] = y > 0.f ? y : 0.f;
}

// ---------------- per-layer SpMM (D=256) -> bf16 hi/lo splits ----------------
__global__ void k_spmm(int buf) {
    const float* __restrict__ H = g_H[buf];
    int n = blockIdx.x, t = threadIdx.x;
    int beg = g_off[n], end = g_off[n + 1];
    float ai0 = 0.f, ao0 = 0.f, ai1 = 0.f, ao1 = 0.f;
    int j = beg;
    for (; j + 4 <= end; j += 4) {
        int2 e0 = g_csrw[j], e1 = g_csrw[j + 1], e2 = g_csrw[j + 2], e3 = g_csrw[j + 3];
        float v0 = __ldg(&H[(e0.x >> 1) * DD + t]);
        float v1 = __ldg(&H[(e1.x >> 1) * DD + t]);
        float v2 = __ldg(&H[(e2.x >> 1) * DD + t]);
        float v3 = __ldg(&H[(e3.x >> 1) * DD + t]);
        float w0 = __int_as_float(e0.y), w1 = __int_as_float(e1.y);
        float w2 = __int_as_float(e2.y), w3 = __int_as_float(e3.y);
        if (e0.x & 1) ai0 = fmaf(w0, v0, ai0); else ao0 = fmaf(w0, v0, ao0);
        if (e1.x & 1) ai1 = fmaf(w1, v1, ai1); else ao1 = fmaf(w1, v1, ao1);
        if (e2.x & 1) ai0 = fmaf(w2, v2, ai0); else ao0 = fmaf(w2, v2, ao0);
        if (e3.x & 1) ai1 = fmaf(w3, v3, ai1); else ao1 = fmaf(w3, v3, ao1);
    }
    for (; j < end; j++) {
        int2 e0 = g_csrw[j];
        float v0 = __ldg(&H[(e0.x >> 1) * DD + t]);
        float w0 = __int_as_float(e0.y);
        if (e0.x & 1) ai0 = fmaf(w0, v0, ai0); else ao0 = fmaf(w0, v0, ao0);
    }
    float ai = ai0 + ai1, ao = ao0 + ao1;
    int o = n * DD + t;
    __nv_bfloat16 h = __float2bfloat16(ai);
    g_Abf[0][o] = h;
    g_Abf[1][o] = __float2bfloat16(ai - __bfloat162float(h));
    h = __float2bfloat16(ao);
    g_Abf[2][o] = h;
    g_Abf[3][o] = __float2bfloat16(ao - __bfloat162float(h));
}

// ---------------- GEMM: 6-segment compensated dual GEMM, bias+LN+ReLU fused --
#define PAD_STRIDE 144
#define FA_BYTES  (128 * PAD_STRIDE)
#define FB_BYTES  (256 * PAD_STRIDE)
#define SMEM_NEED (1024 + 1024 + 2 * FA_BYTES + 2 * FB_BYTES)

__global__ __launch_bounds__(256, 1) void k_gemm_tc(
    const __nv_bfloat16* __restrict__ Wp,   // g_Wp + l*6*DD*DD
    const float* __restrict__ bi, const float* __restrict__ bo,
    const float* __restrict__ lg, const float* __restrict__ lb,
    int outbuf)
{
    extern __shared__ char smem[];
    uint32_t raw = smem_u32(smem);
    uint32_t sb = (raw + 1023u) & ~1023u;   // 1024-aligned base
    int tid = threadIdx.x;
    int wid = tid >> 5, lid = tid & 31;
    int m0 = blockIdx.x * 128;
    const int segA[6] = {0, 0, 1, 2, 2, 3};

#if USE_TCGEN05
    // ---------------- tcgen05 path ----------------
    const uint32_t aoff[2] = {1024u, 1024u + 128 * 128};
    const uint32_t boff[2] = {1024u + 2 * 128 * 128, 1024u + 2 * 128 * 128 + 256 * 128};
    // epilogue params cached in smem after the mbar/tmem region
    char* smp = smem + (sb - raw);
    float* sbias = (float*)(smp + 1024u + 2 * 128 * 128 + 2 * 256 * 128);
    float* sgam  = sbias + 256;
    float* sbet  = sgam + 256;
    sbias[tid] = bi[tid] + bo[tid];
    sgam[tid] = lg[tid];
    sbet[tid] = lb[tid];

    if (wid == 0) {
        asm volatile("tcgen05.alloc.cta_group::1.sync.aligned.shared::cta.b32 [%0], %1;"
                     :: "r"(sb), "r"(512u) : "memory");
    }
    if (tid == 0) { MBAR_INIT(sb + 8, 1); MBAR_INIT(sb + 16, 1); }
    __syncthreads();
    uint32_t tmem;
    asm volatile("ld.shared.b32 %0, [%1];" : "=r"(tmem) : "r"(sb));

    int ph0 = 0, ph1 = 0;
    int chunk = 0;
    // per-thread fixed src/dst roles: A: 4 copies, B: 8 copies
    int arow[4], adst[4], brow[8], bdst[8];
#pragma unroll
    for (int u = 0; u < 4; u++) {
        int idx = u * 256 + tid;
        arow[u] = idx >> 3;
        int q = idx & 7;
        adst[u] = SWZ128(arow[u] * 128 + q * 16);
        arow[u] = arow[u] * DD + q * 8;
    }
#pragma unroll
    for (int u = 0; u < 8; u++) {
        int idx = u * 256 + tid;
        brow[u] = idx >> 3;
        int q = idx & 7;
        bdst[u] = SWZ128(brow[u] * 128 + q * 16);
        brow[u] = brow[u] * DD + q * 8;
    }

    for (int s = 0; s < 6; s++) {
        const __nv_bfloat16* __restrict__ Ag = g_Abf[segA[s]] + (size_t)m0 * DD;
        const __nv_bfloat16* __restrict__ Bg = Wp + (size_t)s * DD * DD;
        for (int c = 0; c < 4; c++) {
            int buf = chunk & 1;
            if (chunk >= 2) {
                if (buf == 0) { MBAR_WAIT(sb + 8, ph0); ph0 ^= 1; }
                else          { MBAR_WAIT(sb + 16, ph1); ph1 ^= 1; }
            }
            int kc = c * 64;
#pragma unroll
            for (int u = 0; u < 4; u++)
                CP_ASYNC16(sb + aoff[buf] + adst[u], Ag + arow[u] + kc);
#pragma unroll
            for (int u = 0; u < 8; u++)
                CP_ASYNC16(sb + boff[buf] + bdst[u], Bg + brow[u] + kc);
            CP_COMMIT;
            CP_WAIT0;
            __syncthreads();
            if (wid == 0) {
                asm volatile("fence.proxy.async.shared::cta;" ::: "memory");
                if (elect_one()) {
                    uint64_t ad = MK_DESC(sb + aoff[buf]);
                    uint64_t bd = MK_DESC(sb + boff[buf]);
#pragma unroll
                    for (int st = 0; st < 4; st++)
                        mma_f16_ss(tmem, ad + st * 2, bd + st * 2, IDESC, !(chunk == 0 && st == 0));
                    asm volatile(
                        "tcgen05.commit.cta_group::1.mbarrier::arrive::one.shared::cluster.b64 [%0];"
                        :: "r"(sb + 8 + buf * 8) : "memory");
                }
            }
            chunk++;
        }
    }
    MBAR_WAIT(sb + 8, ph0);
    MBAR_WAIT(sb + 16, ph1);
    asm volatile("tcgen05.fence::after_thread_sync;" ::: "memory");
    __syncthreads();

    if (wid < 4) {
        int row = m0 + wid * 32 + lid;
        float sum = 0.f, sq = 0.f;
        uint32_t r[32];
        for (int cb = 0; cb < 8; cb++) {
            asm volatile(
                "tcgen05.ld.sync.aligned.32x32b.x32.b32 "
                "{%0,%1,%2,%3,%4,%5,%6,%7,%8,%9,%10,%11,%12,%13,%14,%15,"
                "%16,%17,%18,%19,%20,%21,%22,%23,%24,%25,%26,%27,%28,%29,%30,%31}, [%32];"
                : "=r"(r[0]), "=r"(r[1]), "=r"(r[2]), "=r"(r[3]), "=r"(r[4]), "=r"(r[5]), "=r"(r[6]), "=r"(r[7]),
                  "=r"(r[8]), "=r"(r[9]), "=r"(r[10]), "=r"(r[11]), "=r"(r[12]), "=r"(r[13]), "=r"(r[14]), "=r"(r[15]),
                  "=r"(r[16]), "=r"(r[17]), "=r"(r[18]), "=r"(r[19]), "=r"(r[20]), "=r"(r[21]), "=r"(r[22]), "=r"(r[23]),
                  "=r"(r[24]), "=r"(r[25]), "=r"(r[26]), "=r"(r[27]), "=r"(r[28]), "=r"(r[29]), "=r"(r[30]), "=r"(r[31])
                : "r"(tmem + cb * 32));
            asm volatile("tcgen05.wait::ld.sync.aligned;" ::: "memory");
#pragma unroll
            for (int j = 0; j < 32; j++) {
                int nn = cb * 32 + j;
                float v = __uint_as_float(r[j]) + sbias[nn];
                sum += v; sq += v * v;
            }
        }
        float mean = sum * (1.f / DD);
        float var = sq * (1.f / DD) - mean * mean;
        float rstd = rsqrtf(var + 1e-5f);
        float* __restrict__ Hout = g_H[outbuf];
        for (int cb = 0; cb < 8; cb++) {
            asm volatile(
                "tcgen05.ld.sync.aligned.32x32b.x32.b32 "
                "{%0,%1,%2,%3,%4,%5,%6,%7,%8,%9,%10,%11,%12,%13,%14,%15,"
                "%16,%17,%18,%19,%20,%21,%22,%23,%24,%25,%26,%27,%28,%29,%30,%31}, [%32];"
                : "=r"(r[0]), "=r"(r[1]), "=r"(r[2]), "=r"(r[3]), "=r"(r[4]), "=r"(r[5]), "=r"(r[6]), "=r"(r[7]),
                  "=r"(r[8]), "=r"(r[9]), "=r"(r[10]), "=r"(r[11]), "=r"(r[12]), "=r"(r[13]), "=r"(r[14]), "=r"(r[15]),
                  "=r"(r[16]), "=r"(r[17]), "=r"(r[18]), "=r"(r[19]), "=r"(r[20]), "=r"(r[21]), "=r"(r[22]), "=r"(r[23]),
                  "=r"(r[24]), "=r"(r[25]), "=r"(r[26]), "=r"(r[27]), "=r"(r[28]), "=r"(r[29]), "=r"(r[30]), "=r"(r[31])
                : "r"(tmem + cb * 32));
            asm volatile("tcgen05.wait::ld.sync.aligned;" ::: "memory");
#pragma unroll
            for (int j = 0; j < 32; j++) {
                int nn = cb * 32 + j;
                float v = __uint_as_float(r[j]) + sbias[nn];
                float y = (v - mean) * rstd * sgam[nn] + sbet[nn];
                Hout[(size_t)row * DD + nn] = y > 0.f ? y : 0.f;
            }
        }
    }
    __syncthreads();
    if (wid == 0) {
        asm volatile("tcgen05.relinquish_alloc_permit.cta_group::1.sync.aligned;");
        asm volatile("tcgen05.dealloc.cta_group::1.sync.aligned.b32 %0, %1;" :: "r"(tmem), "r"(512u));
    }
#else
    // ---------------- mma.sync bf16 fallback path (plain sm_103) ----------------
    char* smp = smem + (sb - raw);
    __shared__ float sdsum[128];
    __shared__ float sdsq[128];
    const uint32_t aoff[2] = {1024u, 1024u + FA_BYTES};
    const uint32_t boff[2] = {1024u + 2 * FA_BYTES, 1024u + 2 * FA_BYTES + FB_BYTES};
    int gid = lid >> 2, t4 = lid & 3;
    int wm = wid >> 1, wn = wid & 1;
    int mrow = wm * 32, ncol = wn * 128;
    float acc[2][16][4];
#pragma unroll
    for (int i = 0; i < 2; i++)
#pragma unroll
        for (int j = 0; j < 16; j++)
#pragma unroll
            for (int q = 0; q < 4; q++) acc[i][j][q] = 0.f;

    int chunk = 0;
    for (int s = 0; s < 6; s++) {
        const __nv_bfloat16* __restrict__ Ag = g_Abf[segA[s]];
        const __nv_bfloat16* __restrict__ Bg = Wp + (size_t)s * DD * DD;
        for (int c = 0; c < 4; c++) {
            int buf = chunk & 1;
            int kc = c * 64;
            __syncthreads();
#pragma unroll
            for (int u = 0; u < 4; u++) {
                int idx = u * 256 + tid;
                int row = idx >> 3, q = idx & 7;
                uint4 v = *(const uint4*)(Ag + (size_t)(m0 + row) * DD + kc + q * 8);
                *(uint4*)(smp + aoff[buf] + row * PAD_STRIDE + q * 16) = v;
            }
#pragma unroll
            for (int u = 0; u < 8; u++) {
                int idx = u * 256 + tid;
                int row = idx >> 3, q = idx & 7;
                uint4 v = *(const uint4*)(Bg + (size_t)row * DD + kc + q * 8);
                *(uint4*)(smp + boff[buf] + row * PAD_STRIDE + q * 16) = v;
            }
            __syncthreads();
            const char* ab = smp + aoff[buf];
            const char* bb = smp + boff[buf];
#pragma unroll
            for (int ks = 0; ks < 4; ks++) {
                int kb = ks * 32;
                uint32_t a[2][4];
#pragma unroll
                for (int ma = 0; ma < 2; ma++) {
                    int r0 = mrow + ma * 16 + gid;
                    a[ma][0] = *(const uint32_t*)(ab + r0 * PAD_STRIDE + kb + t4 * 4);
                    a[ma][1] = *(const uint32_t*)(ab + (r0 + 8) * PAD_STRIDE + kb + t4 * 4);
                    a[ma][2] = *(const uint32_t*)(ab + r0 * PAD_STRIDE + kb + 16 + t4 * 4);
                    a[ma][3] = *(const uint32_t*)(ab + (r0 + 8) * PAD_STRIDE + kb + 16 + t4 * 4);
                }
#pragma unroll
                for (int nb = 0; nb < 16; nb++) {
                    int cc = ncol + nb * 8 + gid;
                    uint32_t b0 = *(const uint32_t*)(bb + cc * PAD_STRIDE + kb + t4 * 4);
                    uint32_t b1 = *(const uint32_t*)(bb + cc * PAD_STRIDE + kb + 16 + t4 * 4);
#pragma unroll
                    for (int ma = 0; ma < 2; ma++) {
                        asm volatile(
                            "mma.sync.aligned.m16n8k16.row.col.f32.bf16.bf16.f32 "
                            "{%0,%1,%2,%3}, {%4,%5,%6,%7}, {%8,%9}, {%0,%1,%2,%3};"
                            : "+f"(acc[ma][nb][0]), "+f"(acc[ma][nb][1]),
                              "+f"(acc[ma][nb][2]), "+f"(acc[ma][nb][3])
                            : "r"(a[ma][0]), "r"(a[ma][1]), "r"(a[ma][2]), "r"(a[ma][3]),
                              "r"(b0), "r"(b1));
                    }
                }
            }
            chunk++;
        }
    }
    __syncthreads();
    if (tid < 128) { sdsum[tid] = 0.f; sdsq[tid] = 0.f; }
    __syncthreads();
    float* __restrict__ Hout = g_H[outbuf];
#pragma unroll
    for (int ma = 0; ma < 2; ma++) {
#pragma unroll
        for (int nb = 0; nb < 16; nb++) {
#pragma unroll
            for (int q = 0; q < 4; q++) {
                int row = mrow + ma * 16 + gid + ((q >= 2) ? 8 : 0);
                int col = ncol + nb * 8 + t4 * 2 + (q & 1);
                float v = acc[ma][nb][q] + __ldg(&bi[col]) + __ldg(&bo[col]);
                Hout[(size_t)(m0 + row) * DD + col] = v;
                atomicAdd(&sdsum[row], v);
                atomicAdd(&sdsq[row], v * v);
            }
        }
    }
    __syncthreads();
    for (int r = wid; r < 128; r += 8) {
        float mean = sdsum[r] * (1.f / DD);
        float var = sdsq[r] * (1.f / DD) - mean * mean;
        float rstd = rsqrtf(var + 1e-5f);
#pragma unroll
        for (int u = 0; u < 8; u++) {
            int col = u * 32 + lid;
            float v = Hout[(size_t)(m0 + r) * DD + col];
            float y = (v - mean) * rstd * __ldg(&lg[col]) + __ldg(&lb[col]);
            Hout[(size_t)(m0 + r) * DD + col] = y > 0.f ? y : 0.f;
        }
    }
#endif
}

// ---------------- fragment pooling + LN + mask ----------------
__global__ void k_frag(int buf, const float* __restrict__ fg, const float* __restrict__ fb,
                       float* __restrict__ emb, float* __restrict__ fmask) {
    const float* __restrict__ H = g_H[buf];
    int b = blockIdx.x >> 4;
    int k = blockIdx.x & 15;
    int t = threadIdx.x;
    int lane = t & 31, wd = t >> 5;
    __shared__ float w1[8], w2[8];
    float acc = 0.f;
    int cnt = 0;
    int base = b * NPGX;
    for (int p = 0; p < NPGX; p++) {
        if (g_frag[base + p] == k) {
            acc += H[(base + p) * DD + t];
            cnt++;
        }
    }
    float s1 = acc, s2 = acc * acc;
#pragma unroll
    for (int o = 16; o > 0; o >>= 1) {
        s1 += __shfl_xor_sync(0xFFFFFFFFu, s1, o);
        s2 += __shfl_xor_sync(0xFFFFFFFFu, s2, o);
    }
    if (lane == 0) { w1[wd] = s1; w2[wd] = s2; }
    __syncthreads();
    float t1 = 0.f, t2 = 0.f;
#pragma unroll
    for (int i = 0; i < 8; i++) { t1 += w1[i]; t2 += w2[i]; }
    float m = t1 * (1.f / DD);
    float var = t2 * (1.f / DD) - m * m;
    float y = (acc - m) * rsqrtf(var + 1e-5f) * fg[t] + fb[t];
    emb[(b * KF + k) * DD + t] = y;
    if (t == 0) fmask[b * KF + k] = (cnt > 0) ? 1.f : 0.f;
}

// ---------------- reg loss ----------------
__global__ void k_reg(const float* __restrict__ w0, const float* __restrict__ bo0,
                      const float* __restrict__ W, const float* __restrict__ bo,
                      float* __restrict__ out) {
    __shared__ float r[256];
    int t = threadIdx.x;
    float a = 0.f;
    for (int i = t; i < DIN * DD; i += 256) a += fabsf(w0[i]);
    a += fabsf(bo0[t]);
    for (int i = t; i < 3 * DD * DD; i += 256) a += fabsf(W[i]);
    for (int i = t; i < 3 * DD; i += 256) a += fabsf(bo[i]);
    r[t] = a;
    __syncthreads();
    for (int o = 128; o > 0; o >>= 1) {
        if (t < o) r[t] += r[t + o];
        __syncthreads();
    }
    if (t == 0) out[0] = r[0];
}

// ---------------- launch ----------------
extern "C" void kernel_launch(void* const* d_in, const int* in_sizes, int n_in,
                              void* d_out, int out_size) {
    const float* x   = (const float*)d_in[0];
    const int*   ei  = (const int*)d_in[1];
    const void*  msk = d_in[2];
    const float* s   = (const float*)d_in[3];
    const float* Wi0 = (const float*)d_in[5];
    const float* Wo0 = (const float*)d_in[6];
    const float* bi0 = (const float*)d_in[7];
    const float* bo0 = (const float*)d_in[8];
    const float* Wi  = (const float*)d_in[9];
    const float* Wo  = (const float*)d_in[10];
    const float* bi  = (const float*)d_in[11];
    const float* bo  = (const float*)d_in[12];
    const float* lg  = (const float*)d_in[13];
    const float* lb  = (const float*)d_in[14];
    const float* fg  = (const float*)d_in[15];
    const float* fb  = (const float*)d_in[16];
    float* out = (float*)d_out;

    const int* src = ei;
    const int* dst = ei + NE;

    cudaFuncSetAttribute(k_gemm_tc, cudaFuncAttributeMaxDynamicSharedMemorySize, SMEM_NEED);

    k_init<<<(NN + 255) / 256, 256>>>(s);
    k_deg<<<(NE + 255) / 256, 256>>>(dst);
    k_scan<<<1, 1024>>>((const unsigned char*)msk);
    k_csr<<<(NE + 255) / 256, 256>>>(src, dst, msk);
    k_wprep<<<(3 * DD * DD + 255) / 256, 256>>>(Wi, Wo);

    k_spmm0<<<NN / 8, 256>>>(x);
    k_layer0<<<NN, 256>>>(Wi0, Wo0, bi0, bo0, lg, lb);

    __nv_bfloat16* wp_dev = nullptr;
    cudaGetSymbolAddress((void**)&wp_dev, g_Wp);

    int cur = 0;
    for (int l = 0; l < 3; l++) {
        k_spmm<<<NN, 256>>>(cur);
        k_gemm_tc<<<NN / 128, 256, SMEM_NEED>>>(wp_dev + (size_t)l * 6 * DD * DD,
                                                bi + l * DD, bo + l * DD,
                                                lg + (l + 1) * DD, lb + (l + 1) * DD, 1 - cur);
        cur = 1 - cur;
    }

    k_frag<<<BBG * KF, 256>>>(cur, fg, fb, out, out + BBG * KF * DD);
    k_reg<<<1, 256>>>(Wo0, bo0, Wo, bo, out + BBG * KF * DD + BBG * KF);
}

// round 5
// speedup vs baseline: 3.0289x; 1.1847x over previous
#include <cuda_runtime.h>
#include <cuda_bf16.h>
#include <cstdint>

#define NN   10240
#define NE   320000
#define BBG  64
#define NPGX 160
#define KF   16
#define DIN  25
#define DD   256

#if defined(__CUDA_ARCH_FEAT_SM103_ALL) || defined(__CUDA_ARCH_FEAT_SM100_ALL)
#define USE_TCGEN05 1
#else
#define USE_TCGEN05 0
#endif

// ---------------- device scratch (static, allocation-free) ----------------
__device__ int   g_deg[NN];          // zero-initialized; reset by k_scan each run
__device__ int   g_cur[NN];          // reset by k_scan each run
__device__ int   g_off[NN + 1];
__device__ float g_dinv[NN];
__device__ int2  g_csrw[NE];   // {(src<<1)|mask, bitcast(norm)}
__device__ int   g_frag[NN];
__device__ int   g_mask_is_int;
__device__ float g_H[2][NN * DD];
// bf16 split SpMM outputs: 0=AGI_hi 1=AGI_lo 2=AGO_hi 3=AGO_lo
__device__ __nv_bfloat16 g_Abf[4][NN * DD];
// packed transposed weights: [3 layers][6 segs][256 n][256 k] bf16
__device__ __nv_bfloat16 g_Wp[3 * 6 * DD * DD];

// ---------------- PTX helpers ----------------
__device__ __forceinline__ uint32_t smem_u32(const void* p) {
    uint32_t a;
    asm("{ .reg .u64 t; cvta.to.shared.u64 t, %1; cvt.u32.u64 %0, t; }" : "=r"(a) : "l"(p));
    return a;
}
#define SWZ128(b) ((b) ^ (((b) >> 3) & 0x70))
#define CP_ASYNC16(dst, src) \
    asm volatile("cp.async.cg.shared.global [%0], [%1], 16;" :: "r"(dst), "l"(src) : "memory")
#define CP_COMMIT  asm volatile("cp.async.commit_group;" ::: "memory")
#define CP_WAIT0   asm volatile("cp.async.wait_group 0;" ::: "memory")

#if USE_TCGEN05
__device__ __forceinline__ uint32_t elect_one() {
    uint32_t p;
    asm volatile("{ .reg .pred p; elect.sync _|p, 0xFFFFFFFF; selp.b32 %0, 1, 0, p; }" : "=r"(p));
    return p;
}
#define MBAR_INIT(a, c) asm volatile("mbarrier.init.shared.b64 [%0], %1;" :: "r"(a), "r"(c) : "memory")
#define MBAR_WAIT(a, ph) do { \
    uint32_t _m = (a); uint32_t _p = (ph); uint32_t _d; \
    asm volatile("{ .reg .pred p; mbarrier.try_wait.parity.acquire.cta.shared::cta.b64 p, [%1], %2; selp.b32 %0,1,0,p; }" \
        : "=r"(_d) : "r"(_m), "r"(_p) : "memory"); \
    if (!_d) { \
        asm volatile("{ .reg .pred P1; WL_%=: mbarrier.try_wait.parity.acquire.cta.shared::cta.b64 P1, [%0], %1, 0x989680; @P1 bra.uni WD_%=; bra.uni WL_%=; WD_%=: }" \
            :: "r"(_m), "r"(_p) : "memory"); \
    } } while (0)

static constexpr uint64_t DESC_BASE =
    (uint64_t(2) << 61) | (uint64_t(1) << 46) | (uint64_t(64) << 32) | (uint64_t(1) << 16);
#define MK_DESC(addr) (DESC_BASE | ((uint64_t)((addr) >> 4) & 0x3FFF))

static constexpr uint32_t IDESC = (1u << 4) | (1u << 7) | (1u << 10) | ((256u / 8) << 17) | ((128u / 16) << 24);

__device__ __forceinline__ void mma_f16_ss(uint32_t d, uint64_t ad, uint64_t bd, uint32_t idesc, bool acc) {
    uint32_t en = acc ? 1u : 0u, z = 0;
    asm volatile(
        "{ .reg .pred p; setp.ne.u32 p, %5, 0;\n\t"
        "tcgen05.mma.cta_group::1.kind::f16 [%0], %1, %2, %3, {%4, %4, %4, %4}, p; }"
        :: "r"(d), "l"(ad), "l"(bd), "r"(idesc), "r"(z), "r"(en) : "memory");
}
#endif

// ---------------- fused setup: frag + degree count + weight prep ----------------
// g_deg starts at zero (static init on first run; k_scan re-zeroes it each run).
__global__ void k_setup(const float* __restrict__ s, const int* __restrict__ dst,
                        const float* __restrict__ Wi, const float* __restrict__ Wo) {
    int idx = blockIdx.x * blockDim.x + threadIdx.x;   // grid covers NE
    if (idx < NN) {
        int f = 0;
#pragma unroll
        for (int k = 0; k < KF; k++)
            if (s[idx * KF + k] > 0.5f) f = k;
        g_frag[idx] = f;
    }
    if (idx < 3 * DD * DD) {
        int l = idx / (DD * DD);
        int r = idx - l * DD * DD;
        int k = r / DD;
        int n = r - k * DD;
        float wi = Wi[idx], wo = Wo[idx];
        __nv_bfloat16 wih = __float2bfloat16(wi);
        __nv_bfloat16 wil = __float2bfloat16(wi - __bfloat162float(wih));
        __nv_bfloat16 woh = __float2bfloat16(wo);
        __nv_bfloat16 wol = __float2bfloat16(wo - __bfloat162float(woh));
        size_t base = (size_t)l * 6 * DD * DD + (size_t)n * DD + k;
        g_Wp[base + 0 * DD * DD] = wih;
        g_Wp[base + 1 * DD * DD] = wil;
        g_Wp[base + 2 * DD * DD] = wih;
        g_Wp[base + 3 * DD * DD] = woh;
        g_Wp[base + 4 * DD * DD] = wol;
        g_Wp[base + 5 * DD * DD] = woh;
    }
    if (idx < NE) atomicAdd(&g_deg[dst[idx]], 1);
}

// Single-block scan: off/dinv from deg; resets deg & cur for next graph replay.
__global__ void k_scan(const unsigned char* __restrict__ maskb) {
    __shared__ int warp_tot[32];
    __shared__ int warp_pre[32];
    int t = threadIdx.x;
    int lane = t & 31, wd = t >> 5;
    {
        int idx = t * 4;
        int nz = (int)maskb[idx + 1] | (int)maskb[idx + 2] | (int)maskb[idx + 3];
        if (__syncthreads_or(nz)) { if (t == 0) g_mask_is_int = 0; }
        else                      { if (t == 0) g_mask_is_int = 1; }
    }
    int base = t * 10;
    int loc[10];
    int tot = 0;
#pragma unroll
    for (int i = 0; i < 10; i++) {
        int v = g_deg[base + i];
        g_dinv[base + i] = rsqrtf((float)(v > 0 ? v : 1));
        g_deg[base + i] = 0;
        g_cur[base + i] = 0;
        loc[i] = tot;
        tot += v;
    }
    int inc = tot;
#pragma unroll
    for (int o = 1; o < 32; o <<= 1) {
        int nv = __shfl_up_sync(0xFFFFFFFFu, inc, o);
        if (lane >= o) inc += nv;
    }
    if (lane == 31) warp_tot[wd] = inc;
    __syncthreads();
    if (wd == 0) {
        int v = warp_tot[lane];
        int iv = v;
#pragma unroll
        for (int o = 1; o < 32; o <<= 1) {
            int nv = __shfl_up_sync(0xFFFFFFFFu, iv, o);
            if (lane >= o) iv += nv;
        }
        warp_pre[lane] = iv - v;
    }
    __syncthreads();
    int texcl = inc - tot + warp_pre[wd];
#pragma unroll
    for (int i = 0; i < 10; i++)
        g_off[base + i] = texcl + loc[i];
    if (t == 1023) g_off[NN] = texcl + tot;
}

__global__ void k_csr(const int* __restrict__ src, const int* __restrict__ dst,
                      const void* __restrict__ maskp) {
    int e = blockIdx.x * blockDim.x + threadIdx.x;
    if (e >= NE) return;
    int u = src[e], v = dst[e];
    int mb;
    if (g_mask_is_int) mb = (((const int*)maskp)[e] != 0) ? 1 : 0;
    else               mb = (((const unsigned char*)maskp)[e] != 0) ? 1 : 0;
    int p = g_off[v] + atomicAdd(&g_cur[v], 1);
    g_csrw[p] = make_int2((u << 1) | mb, __float_as_int(g_dinv[u] * g_dinv[v]));
}

// ---------------- fused layer 0: SpMM(25) + GEMM + bias + LN + ReLU ----------
__global__ void k_l0(const float* __restrict__ x,
                     const float* __restrict__ Wi, const float* __restrict__ Wo,
                     const float* __restrict__ bi, const float* __restrict__ bo,
                     const float* __restrict__ lg, const float* __restrict__ lb) {
    int n = blockIdx.x, t = threadIdx.x;
    int lane = t & 31, wd = t >> 5;
    __shared__ float sai8[8][32], sao8[8][32];
    __shared__ float sai[32], sao[32];
    __shared__ float w1[8], w2[8];
    int beg = g_off[n], end = g_off[n + 1];
    float ai = 0.f, ao = 0.f;
    for (int j = beg + wd; j < end; j += 8) {
        int2 e = g_csrw[j];
        float v = (lane < DIN) ? __ldg(&x[(e.x >> 1) * DIN + lane]) : 0.f;
        float w = __int_as_float(e.y);
        if (e.x & 1) ai = fmaf(w, v, ai); else ao = fmaf(w, v, ao);
    }
    if (lane < DIN) { sai8[wd][lane] = ai; sao8[wd][lane] = ao; }
    __syncthreads();
    if (t < DIN) {
        float a = 0.f, b = 0.f;
#pragma unroll
        for (int i = 0; i < 8; i++) { a += sai8[i][t]; b += sao8[i][t]; }
        sai[t] = a; sao[t] = b;
    }
    __syncthreads();
    float acc = bi[t] + bo[t];
#pragma unroll
    for (int j = 0; j < DIN; j++)
        acc += sai[j] * Wi[j * DD + t] + sao[j] * Wo[j * DD + t];
    float s1 = acc, s2 = acc * acc;
#pragma unroll
    for (int o = 16; o > 0; o >>= 1) {
        s1 += __shfl_xor_sync(0xFFFFFFFFu, s1, o);
        s2 += __shfl_xor_sync(0xFFFFFFFFu, s2, o);
    }
    if (lane == 0) { w1[wd] = s1; w2[wd] = s2; }
    __syncthreads();
    float t1 = 0.f, t2 = 0.f;
#pragma unroll
    for (int i = 0; i < 8; i++) { t1 += w1[i]; t2 += w2[i]; }
    float m = t1 * (1.f / DD);
    float var = t2 * (1.f / DD) - m * m;
    float y = (acc - m) * rsqrtf(var + 1e-5f) * lg[t] + lb[t];
    g_H[0][n * DD + t] = y > 0.f ? y : 0.f;
}

// ---------------- per-layer SpMM: 2 nodes/block, float2 gathers -------------
__global__ void k_spmm(int buf) {
    const float2* __restrict__ H2 = (const float2*)g_H[buf];
    int t = threadIdx.x;
    int grp = t >> 7;            // 0/1: which node
    int c2 = t & 127;            // float2 column index (covers 256 floats)
    int n = blockIdx.x * 2 + grp;
    int beg = g_off[n], end = g_off[n + 1];
    float aix = 0.f, aiy = 0.f, aox = 0.f, aoy = 0.f;
    int j = beg;
    // peel to even for int4-aligned edge loads
    if (j < end && (j & 1)) {
        int2 e = g_csrw[j];
        float2 v = __ldg(&H2[(size_t)(e.x >> 1) * 128 + c2]);
        float w = __int_as_float(e.y);
        float wi = (e.x & 1) ? w : 0.f, wo = (e.x & 1) ? 0.f : w;
        aix = fmaf(wi, v.x, aix); aiy = fmaf(wi, v.y, aiy);
        aox = fmaf(wo, v.x, aox); aoy = fmaf(wo, v.y, aoy);
        j++;
    }
    for (; j + 4 <= end; j += 4) {
        int4 p0 = *(const int4*)&g_csrw[j];
        int4 p1 = *(const int4*)&g_csrw[j + 2];
        float2 v0 = __ldg(&H2[(size_t)(p0.x >> 1) * 128 + c2]);
        float2 v1 = __ldg(&H2[(size_t)(p0.z >> 1) * 128 + c2]);
        float2 v2 = __ldg(&H2[(size_t)(p1.x >> 1) * 128 + c2]);
        float2 v3 = __ldg(&H2[(size_t)(p1.z >> 1) * 128 + c2]);
        float w0 = __int_as_float(p0.y), w1 = __int_as_float(p0.w);
        float w2 = __int_as_float(p1.y), w3 = __int_as_float(p1.w);
        float wi0 = (p0.x & 1) ? w0 : 0.f, wo0 = (p0.x & 1) ? 0.f : w0;
        float wi1 = (p0.z & 1) ? w1 : 0.f, wo1 = (p0.z & 1) ? 0.f : w1;
        float wi2 = (p1.x & 1) ? w2 : 0.f, wo2 = (p1.x & 1) ? 0.f : w2;
        float wi3 = (p1.z & 1) ? w3 : 0.f, wo3 = (p1.z & 1) ? 0.f : w3;
        aix = fmaf(wi0, v0.x, aix); aiy = fmaf(wi0, v0.y, aiy);
        aox = fmaf(wo0, v0.x, aox); aoy = fmaf(wo0, v0.y, aoy);
        aix = fmaf(wi1, v1.x, aix); aiy = fmaf(wi1, v1.y, aiy);
        aox = fmaf(wo1, v1.x, aox); aoy = fmaf(wo1, v1.y, aoy);
        aix = fmaf(wi2, v2.x, aix); aiy = fmaf(wi2, v2.y, aiy);
        aox = fmaf(wo2, v2.x, aox); aoy = fmaf(wo2, v2.y, aoy);
        aix = fmaf(wi3, v3.x, aix); aiy = fmaf(wi3, v3.y, aiy);
        aox = fmaf(wo3, v3.x, aox); aoy = fmaf(wo3, v3.y, aoy);
    }
    for (; j < end; j++) {
        int2 e = g_csrw[j];
        float2 v = __ldg(&H2[(size_t)(e.x >> 1) * 128 + c2]);
        float w = __int_as_float(e.y);
        float wi = (e.x & 1) ? w : 0.f, wo = (e.x & 1) ? 0.f : w;
        aix = fmaf(wi, v.x, aix); aiy = fmaf(wi, v.y, aiy);
        aox = fmaf(wo, v.x, aox); aoy = fmaf(wo, v.y, aoy);
    }
    int o = n * 128 + c2;   // bf16x2 index
    __nv_bfloat16 hx = __float2bfloat16(aix), hy = __float2bfloat16(aiy);
    ((__nv_bfloat162*)g_Abf[0])[o] = __nv_bfloat162(hx, hy);
    ((__nv_bfloat162*)g_Abf[1])[o] = __nv_bfloat162(
        __float2bfloat16(aix - __bfloat162float(hx)),
        __float2bfloat16(aiy - __bfloat162float(hy)));
    hx = __float2bfloat16(aox); hy = __float2bfloat16(aoy);
    ((__nv_bfloat162*)g_Abf[2])[o] = __nv_bfloat162(hx, hy);
    ((__nv_bfloat162*)g_Abf[3])[o] = __nv_bfloat162(
        __float2bfloat16(aox - __bfloat162float(hx)),
        __float2bfloat16(aoy - __bfloat162float(hy)));
}

// ---------------- GEMM: 6-segment compensated dual GEMM, bias+LN+ReLU fused --
#define PAD_STRIDE 144
#define FA_BYTES  (128 * PAD_STRIDE)
#define FB_BYTES  (256 * PAD_STRIDE)
#define SMEM_NEED (1024 + 1024 + 2 * FA_BYTES + 2 * FB_BYTES)

__global__ __launch_bounds__(256, 1) void k_gemm_tc(
    const __nv_bfloat16* __restrict__ Wp,   // g_Wp + l*6*DD*DD
    const float* __restrict__ bi, const float* __restrict__ bo,
    const float* __restrict__ lg, const float* __restrict__ lb,
    int outbuf)
{
    extern __shared__ char smem[];
    uint32_t raw = smem_u32(smem);
    uint32_t sb = (raw + 1023u) & ~1023u;
    int tid = threadIdx.x;
    int wid = tid >> 5, lid = tid & 31;
    int m0 = blockIdx.x * 128;
    const int segA[6] = {0, 0, 1, 2, 2, 3};

#if USE_TCGEN05
    const uint32_t aoff[2] = {1024u, 1024u + 128 * 128};
    const uint32_t boff[2] = {1024u + 2 * 128 * 128, 1024u + 2 * 128 * 128 + 256 * 128};
    char* smp = smem + (sb - raw);
    float* sbias = (float*)(smp + 1024u + 2 * 128 * 128 + 2 * 256 * 128);
    float* sgam  = sbias + 256;
    float* sbet  = sgam + 256;
    sbias[tid] = bi[tid] + bo[tid];
    sgam[tid] = lg[tid];
    sbet[tid] = lb[tid];

    if (wid == 0) {
        asm volatile("tcgen05.alloc.cta_group::1.sync.aligned.shared::cta.b32 [%0], %1;"
                     :: "r"(sb), "r"(512u) : "memory");
    }
    if (tid == 0) { MBAR_INIT(sb + 8, 1); MBAR_INIT(sb + 16, 1); }
    __syncthreads();
    uint32_t tmem;
    asm volatile("ld.shared.b32 %0, [%1];" : "=r"(tmem) : "r"(sb));

    int ph0 = 0, ph1 = 0;
    int chunk = 0;
    int arow[4], adst[4], brow[8], bdst[8];
#pragma unroll
    for (int u = 0; u < 4; u++) {
        int idx = u * 256 + tid;
        arow[u] = idx >> 3;
        int q = idx & 7;
        adst[u] = SWZ128(arow[u] * 128 + q * 16);
        arow[u] = arow[u] * DD + q * 8;
    }
#pragma unroll
    for (int u = 0; u < 8; u++) {
        int idx = u * 256 + tid;
        brow[u] = idx >> 3;
        int q = idx & 7;
        bdst[u] = SWZ128(brow[u] * 128 + q * 16);
        brow[u] = brow[u] * DD + q * 8;
    }

    for (int s = 0; s < 6; s++) {
        const __nv_bfloat16* __restrict__ Ag = g_Abf[segA[s]] + (size_t)m0 * DD;
        const __nv_bfloat16* __restrict__ Bg = Wp + (size_t)s * DD * DD;
        for (int c = 0; c < 4; c++) {
            int buf = chunk & 1;
            if (chunk >= 2) {
                if (buf == 0) { MBAR_WAIT(sb + 8, ph0); ph0 ^= 1; }
                else          { MBAR_WAIT(sb + 16, ph1); ph1 ^= 1; }
            }
            int kc = c * 64;
#pragma unroll
            for (int u = 0; u < 4; u++)
                CP_ASYNC16(sb + aoff[buf] + adst[u], Ag + arow[u] + kc);
#pragma unroll
            for (int u = 0; u < 8; u++)
                CP_ASYNC16(sb + boff[buf] + bdst[u], Bg + brow[u] + kc);
            CP_COMMIT;
            CP_WAIT0;
            __syncthreads();
            if (wid == 0) {
                asm volatile("fence.proxy.async.shared::cta;" ::: "memory");
                if (elect_one()) {
                    uint64_t ad = MK_DESC(sb + aoff[buf]);
                    uint64_t bd = MK_DESC(sb + boff[buf]);
#pragma unroll
                    for (int st = 0; st < 4; st++)
                        mma_f16_ss(tmem, ad + st * 2, bd + st * 2, IDESC, !(chunk == 0 && st == 0));
                    asm volatile(
                        "tcgen05.commit.cta_group::1.mbarrier::arrive::one.shared::cluster.b64 [%0];"
                        :: "r"(sb + 8 + buf * 8) : "memory");
                }
            }
            chunk++;
        }
    }
    MBAR_WAIT(sb + 8, ph0);
    MBAR_WAIT(sb + 16, ph1);
    asm volatile("tcgen05.fence::after_thread_sync;" ::: "memory");
    __syncthreads();

    if (wid < 4) {
        int row = m0 + wid * 32 + lid;
        float sum = 0.f, sq = 0.f;
        uint32_t r[32];
        for (int cb = 0; cb < 8; cb++) {
            asm volatile(
                "tcgen05.ld.sync.aligned.32x32b.x32.b32 "
                "{%0,%1,%2,%3,%4,%5,%6,%7,%8,%9,%10,%11,%12,%13,%14,%15,"
                "%16,%17,%18,%19,%20,%21,%22,%23,%24,%25,%26,%27,%28,%29,%30,%31}, [%32];"
                : "=r"(r[0]), "=r"(r[1]), "=r"(r[2]), "=r"(r[3]), "=r"(r[4]), "=r"(r[5]), "=r"(r[6]), "=r"(r[7]),
                  "=r"(r[8]), "=r"(r[9]), "=r"(r[10]), "=r"(r[11]), "=r"(r[12]), "=r"(r[13]), "=r"(r[14]), "=r"(r[15]),
                  "=r"(r[16]), "=r"(r[17]), "=r"(r[18]), "=r"(r[19]), "=r"(r[20]), "=r"(r[21]), "=r"(r[22]), "=r"(r[23]),
                  "=r"(r[24]), "=r"(r[25]), "=r"(r[26]), "=r"(r[27]), "=r"(r[28]), "=r"(r[29]), "=r"(r[30]), "=r"(r[31])
                : "r"(tmem + cb * 32));
            asm volatile("tcgen05.wait::ld.sync.aligned;" ::: "memory");
#pragma unroll
            for (int j = 0; j < 32; j++) {
                int nn = cb * 32 + j;
                float v = __uint_as_float(r[j]) + sbias[nn];
                sum += v; sq += v * v;
            }
        }
        float mean = sum * (1.f / DD);
        float var = sq * (1.f / DD) - mean * mean;
        float rstd = rsqrtf(var + 1e-5f);
        float* __restrict__ Hout = g_H[outbuf];
        for (int cb = 0; cb < 8; cb++) {
            asm volatile(
                "tcgen05.ld.sync.aligned.32x32b.x32.b32 "
                "{%0,%1,%2,%3,%4,%5,%6,%7,%8,%9,%10,%11,%12,%13,%14,%15,"
                "%16,%17,%18,%19,%20,%21,%22,%23,%24,%25,%26,%27,%28,%29,%30,%31}, [%32];"
                : "=r"(r[0]), "=r"(r[1]), "=r"(r[2]), "=r"(r[3]), "=r"(r[4]), "=r"(r[5]), "=r"(r[6]), "=r"(r[7]),
                  "=r"(r[8]), "=r"(r[9]), "=r"(r[10]), "=r"(r[11]), "=r"(r[12]), "=r"(r[13]), "=r"(r[14]), "=r"(r[15]),
                  "=r"(r[16]), "=r"(r[17]), "=r"(r[18]), "=r"(r[19]), "=r"(r[20]), "=r"(r[21]), "=r"(r[22]), "=r"(r[23]),
                  "=r"(r[24]), "=r"(r[25]), "=r"(r[26]), "=r"(r[27]), "=r"(r[28]), "=r"(r[29]), "=r"(r[30]), "=r"(r[31])
                : "r"(tmem + cb * 32));
            asm volatile("tcgen05.wait::ld.sync.aligned;" ::: "memory");
#pragma unroll
            for (int j = 0; j < 32; j++) {
                int nn = cb * 32 + j;
                float v = __uint_as_float(r[j]) + sbias[nn];
                float y = (v - mean) * rstd * sgam[nn] + sbet[nn];
                Hout[(size_t)row * DD + nn] = y > 0.f ? y : 0.f;
            }
        }
    }
    __syncthreads();
    if (wid == 0) {
        asm volatile("tcgen05.relinquish_alloc_permit.cta_group::1.sync.aligned;");
        asm volatile("tcgen05.dealloc.cta_group::1.sync.aligned.b32 %0, %1;" :: "r"(tmem), "r"(512u));
    }
#else
    // ---------------- mma.sync bf16 fallback path (plain sm_103) ----------------
    char* smp = smem + (sb - raw);
    __shared__ float sdsum[128];
    __shared__ float sdsq[128];
    const uint32_t aoff[2] = {1024u, 1024u + FA_BYTES};
    const uint32_t boff[2] = {1024u + 2 * FA_BYTES, 1024u + 2 * FA_BYTES + FB_BYTES};
    int gid = lid >> 2, t4 = lid & 3;
    int wm = wid >> 1, wn = wid & 1;
    int mrow = wm * 32, ncol = wn * 128;
    float acc[2][16][4];
#pragma unroll
    for (int i = 0; i < 2; i++)
#pragma unroll
        for (int j = 0; j < 16; j++)
#pragma unroll
            for (int q = 0; q < 4; q++) acc[i][j][q] = 0.f;

    int chunk = 0;
    for (int s = 0; s < 6; s++) {
        const __nv_bfloat16* __restrict__ Ag = g_Abf[segA[s]];
        const __nv_bfloat16* __restrict__ Bg = Wp + (size_t)s * DD * DD;
        for (int c = 0; c < 4; c++) {
            int buf = chunk & 1;
            int kc = c * 64;
            __syncthreads();
#pragma unroll
            for (int u = 0; u < 4; u++) {
                int idx = u * 256 + tid;
                int row = idx >> 3, q = idx & 7;
                uint4 v = *(const uint4*)(Ag + (size_t)(m0 + row) * DD + kc + q * 8);
                *(uint4*)(smp + aoff[buf] + row * PAD_STRIDE + q * 16) = v;
            }
#pragma unroll
            for (int u = 0; u < 8; u++) {
                int idx = u * 256 + tid;
                int row = idx >> 3, q = idx & 7;
                uint4 v = *(const uint4*)(Bg + (size_t)row * DD + kc + q * 8);
                *(uint4*)(smp + boff[buf] + row * PAD_STRIDE + q * 16) = v;
            }
            __syncthreads();
            const char* ab = smp + aoff[buf];
            const char* bb = smp + boff[buf];
#pragma unroll
            for (int ks = 0; ks < 4; ks++) {
                int kb = ks * 32;
                uint32_t a[2][4];
#pragma unroll
                for (int ma = 0; ma < 2; ma++) {
                    int r0 = mrow + ma * 16 + gid;
                    a[ma][0] = *(const uint32_t*)(ab + r0 * PAD_STRIDE + kb + t4 * 4);
                    a[ma][1] = *(const uint32_t*)(ab + (r0 + 8) * PAD_STRIDE + kb + t4 * 4);
                    a[ma][2] = *(const uint32_t*)(ab + r0 * PAD_STRIDE + kb + 16 + t4 * 4);
                    a[ma][3] = *(const uint32_t*)(ab + (r0 + 8) * PAD_STRIDE + kb + 16 + t4 * 4);
                }
#pragma unroll
                for (int nb = 0; nb < 16; nb++) {
                    int cc = ncol + nb * 8 + gid;
                    uint32_t b0 = *(const uint32_t*)(bb + cc * PAD_STRIDE + kb + t4 * 4);
                    uint32_t b1 = *(const uint32_t*)(bb + cc * PAD_STRIDE + kb + 16 + t4 * 4);
#pragma unroll
                    for (int ma = 0; ma < 2; ma++) {
                        asm volatile(
                            "mma.sync.aligned.m16n8k16.row.col.f32.bf16.bf16.f32 "
                            "{%0,%1,%2,%3}, {%4,%5,%6,%7}, {%8,%9}, {%0,%1,%2,%3};"
                            : "+f"(acc[ma][nb][0]), "+f"(acc[ma][nb][1]),
                              "+f"(acc[ma][nb][2]), "+f"(acc[ma][nb][3])
                            : "r"(a[ma][0]), "r"(a[ma][1]), "r"(a[ma][2]), "r"(a[ma][3]),
                              "r"(b0), "r"(b1));
                    }
                }
            }
            chunk++;
        }
    }
    __syncthreads();
    if (tid < 128) { sdsum[tid] = 0.f; sdsq[tid] = 0.f; }
    __syncthreads();
    float* __restrict__ Hout = g_H[outbuf];
#pragma unroll
    for (int ma = 0; ma < 2; ma++) {
#pragma unroll
        for (int nb = 0; nb < 16; nb++) {
#pragma unroll
            for (int q = 0; q < 4; q++) {
                int row = mrow + ma * 16 + gid + ((q >= 2) ? 8 : 0);
                int col = ncol + nb * 8 + t4 * 2 + (q & 1);
                float v = acc[ma][nb][q] + __ldg(&bi[col]) + __ldg(&bo[col]);
                Hout[(size_t)(m0 + row) * DD + col] = v;
                atomicAdd(&sdsum[row], v);
                atomicAdd(&sdsq[row], v * v);
            }
        }
    }
    __syncthreads();
    for (int r = wid; r < 128; r += 8) {
        float mean = sdsum[r] * (1.f / DD);
        float var = sdsq[r] * (1.f / DD) - mean * mean;
        float rstd = rsqrtf(var + 1e-5f);
#pragma unroll
        for (int u = 0; u < 8; u++) {
            int col = u * 32 + lid;
            float v = Hout[(size_t)(m0 + r) * DD + col];
            float y = (v - mean) * rstd * __ldg(&lg[col]) + __ldg(&lb[col]);
            Hout[(size_t)(m0 + r) * DD + col] = y > 0.f ? y : 0.f;
        }
    }
#endif
}

// ---------------- fragment pooling + LN + mask + reg loss (fused) ------------
__global__ void k_frag(int buf, const float* __restrict__ fg, const float* __restrict__ fb,
                       float* __restrict__ emb, float* __restrict__ fmask,
                       const float* __restrict__ w0r, const float* __restrict__ bo0r,
                       const float* __restrict__ Wr, const float* __restrict__ bor,
                       float* __restrict__ regout) {
    int t = threadIdx.x;
    if (blockIdx.x == BBG) {
        // reg-loss block
        __shared__ float r[256];
        float a = 0.f;
        for (int i = t; i < DIN * DD; i += 256) a += fabsf(w0r[i]);
        a += fabsf(bo0r[t]);
        for (int i = t; i < 3 * DD * DD; i += 256) a += fabsf(Wr[i]);
        for (int i = t; i < 3 * DD; i += 256) a += fabsf(bor[i]);
        r[t] = a;
        __syncthreads();
        for (int o = 128; o > 0; o >>= 1) {
            if (t < o) r[t] += r[t + o];
            __syncthreads();
        }
        if (t == 0) regout[0] = r[0];
        return;
    }
    const float* __restrict__ H = g_H[buf];
    int b = blockIdx.x;
    int lane = t & 31, wd = t >> 5;
    __shared__ float sacc[KF][DD];
    __shared__ int   sfrag[NPGX];
    __shared__ int   scnt[KF];
    __shared__ float w1[8], w2[8];
#pragma unroll
    for (int kf = 0; kf < KF; kf++) sacc[kf][t] = 0.f;
    if (t < NPGX) sfrag[t] = g_frag[b * NPGX + t];
    __syncthreads();
    int base = b * NPGX;
    int cnt_local = 0;
    for (int p = 0; p < NPGX; p++) {
        int f = sfrag[p];
        float v = H[(size_t)(base + p) * DD + t];
        sacc[f][t] += v;
        if (t == f) cnt_local++;
    }
    if (t < KF) scnt[t] = cnt_local;
    __syncthreads();
    for (int kf = 0; kf < KF; kf++) {
        float acc = sacc[kf][t];
        float s1 = acc, s2 = acc * acc;
#pragma unroll
        for (int o = 16; o > 0; o >>= 1) {
            s1 += __shfl_xor_sync(0xFFFFFFFFu, s1, o);
            s2 += __shfl_xor_sync(0xFFFFFFFFu, s2, o);
        }
        if (lane == 0) { w1[wd] = s1; w2[wd] = s2; }
        __syncthreads();
        float t1 = 0.f, t2 = 0.f;
#pragma unroll
        for (int i = 0; i < 8; i++) { t1 += w1[i]; t2 += w2[i]; }
        float m = t1 * (1.f / DD);
        float var = t2 * (1.f / DD) - m * m;
        float y = (acc - m) * rsqrtf(var + 1e-5f) * fg[t] + fb[t];
        emb[(size_t)(b * KF + kf) * DD + t] = y;
        if (t == 0) fmask[b * KF + kf] = (scnt[kf] > 0) ? 1.f : 0.f;
        __syncthreads();
    }
}

// ---------------- launch ----------------
extern "C" void kernel_launch(void* const* d_in, const int* in_sizes, int n_in,
                              void* d_out, int out_size) {
    const float* x   = (const float*)d_in[0];
    const int*   ei  = (const int*)d_in[1];
    const void*  msk = d_in[2];
    const float* s   = (const float*)d_in[3];
    const float* Wi0 = (const float*)d_in[5];
    const float* Wo0 = (const float*)d_in[6];
    const float* bi0 = (const float*)d_in[7];
    const float* bo0 = (const float*)d_in[8];
    const float* Wi  = (const float*)d_in[9];
    const float* Wo  = (const float*)d_in[10];
    const float* bi  = (const float*)d_in[11];
    const float* bo  = (const float*)d_in[12];
    const float* lg  = (const float*)d_in[13];
    const float* lb  = (const float*)d_in[14];
    const float* fg  = (const float*)d_in[15];
    const float* fb  = (const float*)d_in[16];
    float* out = (float*)d_out;

    const int* src = ei;
    const int* dst = ei + NE;

    cudaFuncSetAttribute(k_gemm_tc, cudaFuncAttributeMaxDynamicSharedMemorySize, SMEM_NEED);

    k_setup<<<(NE + 255) / 256, 256>>>(s, dst, Wi, Wo);
    k_scan<<<1, 1024>>>((const unsigned char*)msk);
    k_csr<<<(NE + 255) / 256, 256>>>(src, dst, msk);
    k_l0<<<NN, 256>>>(x, Wi0, Wo0, bi0, bo0, lg, lb);

    __nv_bfloat16* wp_dev = nullptr;
    cudaGetSymbolAddress((void**)&wp_dev, g_Wp);

    int cur = 0;
    for (int l = 0; l < 3; l++) {
        k_spmm<<<NN / 2, 256>>>(cur);
        k_gemm_tc<<<NN / 128, 256, SMEM_NEED>>>(wp_dev + (size_t)l * 6 * DD * DD,
                                                bi + l * DD, bo + l * DD,
                                                lg + (l + 1) * DD, lb + (l + 1) * DD, 1 - cur);
        cur = 1 - cur;
    }

    k_frag<<<BBG + 1, 256>>>(cur, fg, fb, out, out + BBG * KF * DD,
                             Wo0, bo0, Wo, bo, out + BBG * KF * DD + BBG * KF);
}